// round 1
// baseline (speedup 1.0000x reference)
#include <cuda_runtime.h>
#include <cstdint>

// ---------------- scratch (device globals: allocation-free) ----------------
__device__ __align__(256) float g_y1[4 * 64 * 32 * 32];
__device__ __align__(256) float g_y2c[4 * 64 * 16 * 16];
__device__ __align__(256) float g_y3[4 * 64 * 8 * 8];
__device__ __align__(256) float g_am[4 * 64 * 4096];       // gated input, [b][c][hw]
__device__ __align__(256) float g_theta[4 * 4096 * 32];    // [b][i][c]
__device__ __align__(256) float g_phi[4 * 4096 * 32];      // [b][j][c]
__device__ __align__(256) float g_gx[4 * 4096 * 32];       // [b][j][c] (later /= colsum)
__device__ __align__(256) float g_colsum[4 * 4096];
__device__ __align__(256) float g_E[67108864];             // exp(f), [b][i][j] (268MB)
__device__ __align__(256) float g_y2a[4 * 4096 * 32];      // attention out, [b][i][c]

// ---------------- conv3x3 stride2 pad1, C=64 -> C=64 ----------------
// block: 128 threads = 32 pixels x 4 co-groups (16 co each)
__global__ void conv3x3_s2(const float* __restrict__ in, float* __restrict__ out,
                           const float* __restrict__ w, const float* __restrict__ bias,
                           int Hin, int Hout, int do_lrelu) {
    __shared__ float ws[16 * 64 * 9];  // [ci_local][co][9]  (36KB)
    int t = threadIdx.x;
    int pxl = t & 31, cog = t >> 5;
    int gpx = blockIdx.x * 32 + pxl;
    int hw2 = Hout * Hout;
    int b = gpx / hw2;
    int ohw = gpx - b * hw2;
    int oh = ohw / Hout, ow = ohw - oh * Hout;

    float acc[16];
#pragma unroll
    for (int c = 0; c < 16; c++) acc[c] = bias[cog * 16 + c];

    for (int cc = 0; cc < 64; cc += 16) {
        __syncthreads();
        for (int l = t; l < 16 * 64 * 9; l += 128) {
            int ci_l = l / 576;
            int rem = l - ci_l * 576;
            int co = rem / 9;
            int k = rem - co * 9;
            ws[l] = w[(co * 64 + cc + ci_l) * 9 + k];
        }
        __syncthreads();
        for (int ci_l = 0; ci_l < 16; ci_l++) {
            const float* inp = in + (b * 64 + cc + ci_l) * Hin * Hin;
            float v[9];
#pragma unroll
            for (int kh = 0; kh < 3; kh++)
#pragma unroll
                for (int kw = 0; kw < 3; kw++) {
                    int ih = 2 * oh - 1 + kh;
                    int iw = 2 * ow - 1 + kw;
                    bool ok = (ih >= 0) && (ih < Hin) && (iw >= 0) && (iw < Hin);
                    v[kh * 3 + kw] = ok ? inp[ih * Hin + iw] : 0.0f;
                }
            const float* wsp = ws + ci_l * 576 + cog * 16 * 9;
#pragma unroll
            for (int c = 0; c < 16; c++) {
#pragma unroll
                for (int k = 0; k < 9; k++) acc[c] += v[k] * wsp[c * 9 + k];
            }
        }
    }
    float* op = out + b * 64 * hw2 + ohw;
#pragma unroll
    for (int c = 0; c < 16; c++) {
        float vv = acc[c];
        if (do_lrelu) vv = (vv >= 0.0f) ? vv : 0.2f * vv;
        op[(cog * 16 + c) * hw2] = vv;
    }
}

// ---------------- bilinear 8->64 upsample + sigmoid gate ----------------
__global__ void upgate(const float* __restrict__ y3, const float* __restrict__ x,
                       float* __restrict__ am) {
    int idx = blockIdx.x * 256 + threadIdx.x;  // over 4*64*4096
    int hw = idx & 4095;
    int bc = idx >> 12;
    int h = hw >> 6, w = hw & 63;
    float sh = (h + 0.5f) * 0.125f - 0.5f;
    float sw = (w + 0.5f) * 0.125f - 0.5f;
    int h0 = (int)floorf(sh);
    int w0 = (int)floorf(sw);
    float fh = sh - (float)h0;
    float fw = sw - (float)w0;
    int h0c = min(max(h0, 0), 7), h1c = min(max(h0 + 1, 0), 7);
    int w0c = min(max(w0, 0), 7), w1c = min(max(w0 + 1, 0), 7);
    const float* yp = y3 + bc * 64;
    float v = (1.0f - fh) * ((1.0f - fw) * yp[h0c * 8 + w0c] + fw * yp[h0c * 8 + w1c]) +
              fh * ((1.0f - fw) * yp[h1c * 8 + w0c] + fw * yp[h1c * 8 + w1c]);
    float s = 1.0f / (1.0f + __expf(-v));
    am[idx] = s * x[idx];
}

// ---------------- 1x1 projections: am -> theta/phi/g, transposed [b][i][c] ----------------
__global__ void proj1x1(const float* __restrict__ am,
                        const float* __restrict__ thw, const float* __restrict__ thb,
                        const float* __restrict__ phw, const float* __restrict__ phb,
                        const float* __restrict__ gw, const float* __restrict__ gb,
                        float* __restrict__ theta, float* __restrict__ phi,
                        float* __restrict__ gx) {
    __shared__ float ws[3][32 * 64];
    __shared__ float bs[3][32];
    int t = threadIdx.x;  // 256
    for (int l = t; l < 3 * 2048; l += 256) {
        int o = l / 2048, r = l - o * 2048;
        const float* src = (o == 0) ? thw : ((o == 1) ? phw : gw);
        ws[o][r] = src[r];
    }
    if (t < 96) {
        int o = t / 32, c = t & 31;
        const float* src = (o == 0) ? thb : ((o == 1) ? phb : gb);
        bs[o][c] = src[c];
    }
    __syncthreads();
    int gi = blockIdx.x * 256 + t;  // over 4*4096
    int b = gi >> 12;
    int pix = gi & 4095;
    const float* ap = g_am + b * 64 * 4096 + pix;
    (void)am;
    for (int o = 0; o < 3; o++) {
        float acc[32];
#pragma unroll
        for (int c = 0; c < 32; c++) acc[c] = bs[o][c];
        for (int ci = 0; ci < 64; ci++) {
            float a = ap[ci * 4096];
#pragma unroll
            for (int c = 0; c < 32; c++) acc[c] += a * ws[o][c * 64 + ci];
        }
        float* outp = ((o == 0) ? theta : ((o == 1) ? phi : gx)) + (size_t)gi * 32;
#pragma unroll
        for (int c = 0; c < 32; c++) outp[c] = acc[c];
    }
}

// ---------------- GEMM1: E = exp(theta_t @ phi_t^T), + column sums ----------------
// grid (32 jTiles, 32 iTiles, 4 b), block 256, tile 128x128, micro 8x8 interleaved
__global__ __launch_bounds__(256, 2) void gemm1_exp(const float* __restrict__ theta,
                                                    const float* __restrict__ phi,
                                                    float* __restrict__ E,
                                                    float* __restrict__ colsum) {
    __shared__ float As[128 * 33];
    __shared__ float Bs[128 * 33];
    int t = threadIdx.x;
    int b = blockIdx.z;
    int iBase = blockIdx.y * 128, jBase = blockIdx.x * 128;
    const float4* Ag = (const float4*)(theta + ((size_t)b * 4096 + iBase) * 32);
    const float4* Bg = (const float4*)(phi + ((size_t)b * 4096 + jBase) * 32);
#pragma unroll
    for (int v = 0; v < 4; v++) {
        int l = t + v * 256;  // quad id in [0,1024)
        int row = l >> 3, q = l & 7;
        float4 d = Ag[l];
        float* s = &As[row * 33 + q * 4];
        s[0] = d.x; s[1] = d.y; s[2] = d.z; s[3] = d.w;
        float4 e = Bg[l];
        float* s2 = &Bs[row * 33 + q * 4];
        s2[0] = e.x; s2[1] = e.y; s2[2] = e.z; s2[3] = e.w;
    }
    __syncthreads();
    int tx = t & 15, ty = t >> 4;
    float acc[8][8];
#pragma unroll
    for (int u = 0; u < 8; u++)
#pragma unroll
        for (int v = 0; v < 8; v++) acc[u][v] = 0.0f;

#pragma unroll 8
    for (int k = 0; k < 32; k++) {
        float rA[8], rB[8];
#pragma unroll
        for (int u = 0; u < 8; u++) rA[u] = As[(ty + u * 16) * 33 + k];
#pragma unroll
        for (int v = 0; v < 8; v++) rB[v] = Bs[(tx + v * 16) * 33 + k];
#pragma unroll
        for (int u = 0; u < 8; u++)
#pragma unroll
            for (int v = 0; v < 8; v++) acc[u][v] += rA[u] * rB[v];
    }

    float csum[8];
#pragma unroll
    for (int v = 0; v < 8; v++) csum[v] = 0.0f;
#pragma unroll
    for (int u = 0; u < 8; u++) {
        float* Erow = E + ((size_t)(b * 4096 + iBase + ty + u * 16)) * 4096 + jBase;
#pragma unroll
        for (int v = 0; v < 8; v++) {
            float e = __expf(acc[u][v]);
            csum[v] += e;
            Erow[tx + v * 16] = e;
        }
    }
    __syncthreads();
    float* red = As;  // reuse: [16 ty][128 cols]
#pragma unroll
    for (int v = 0; v < 8; v++) red[ty * 128 + tx + v * 16] = csum[v];
    __syncthreads();
    if (t < 128) {
        float s = 0.0f;
#pragma unroll
        for (int r = 0; r < 16; r++) s += red[r * 128 + t];
        atomicAdd(&colsum[b * 4096 + jBase + t], s);
    }
}

// ---------------- g2 = g / colsum[j] ----------------
__global__ void g2div(float* __restrict__ gx, const float* __restrict__ colsum) {
    int idx = blockIdx.x * 256 + threadIdx.x;  // 4*4096*32
    gx[idx] = gx[idx] / colsum[idx >> 5];
}

// ---------------- GEMM2: y2[b,i,c] += sum_j E[i,j] * g2[j,c]  (split-K atomic) ----------------
// grid (32 iTiles, 4 jSplit, 4 b), block 256 = (tx:8 c-groups x4) x (ty:32 i-groups x4)
__global__ __launch_bounds__(256, 2) void gemm2_av(const float* __restrict__ E,
                                                   const float* __restrict__ g2,
                                                   float* __restrict__ y2) {
    __shared__ float Es[128 * 65];
    __shared__ float Gs[64 * 33];
    int t = threadIdx.x;
    int tx = t & 7, ty = t >> 3;
    int b = blockIdx.z;
    int iBase = blockIdx.x * 128;
    int jStart = blockIdx.y * 1024;
    float acc[4][4];
#pragma unroll
    for (int u = 0; u < 4; u++)
#pragma unroll
        for (int v = 0; v < 4; v++) acc[u][v] = 0.0f;

    for (int j0 = jStart; j0 < jStart + 1024; j0 += 64) {
        __syncthreads();
        // load E tile 128x64
#pragma unroll
        for (int v = 0; v < 8; v++) {
            int l = t + v * 256;  // quad in [0,2048)
            int row = l >> 4, q = l & 15;
            float4 d = *(const float4*)(E + ((size_t)(b * 4096 + iBase + row)) * 4096 + j0 + q * 4);
            float* s = &Es[row * 65 + q * 4];
            s[0] = d.x; s[1] = d.y; s[2] = d.z; s[3] = d.w;
        }
        // load g2 tile 64x32
#pragma unroll
        for (int v = 0; v < 2; v++) {
            int l = t + v * 256;  // quad in [0,512)
            int row = l >> 3, q = l & 7;
            float4 d = *(const float4*)(g2 + (size_t)(b * 4096 + j0 + row) * 32 + q * 4);
            float* s = &Gs[row * 33 + q * 4];
            s[0] = d.x; s[1] = d.y; s[2] = d.z; s[3] = d.w;
        }
        __syncthreads();
#pragma unroll 8
        for (int jj = 0; jj < 64; jj++) {
            float rA[4], rB[4];
#pragma unroll
            for (int u = 0; u < 4; u++) rA[u] = Es[(ty + u * 32) * 65 + jj];
#pragma unroll
            for (int v = 0; v < 4; v++) rB[v] = Gs[jj * 33 + tx + v * 8];
#pragma unroll
            for (int u = 0; u < 4; u++)
#pragma unroll
                for (int v = 0; v < 4; v++) acc[u][v] += rA[u] * rB[v];
        }
    }
#pragma unroll
    for (int u = 0; u < 4; u++)
#pragma unroll
        for (int v = 0; v < 4; v++)
            atomicAdd(&y2[(size_t)(b * 4096 + iBase + ty + u * 32) * 32 + tx + v * 8],
                      acc[u][v]);
}

// ---------------- epilogue: out = (W@y2 + wb + am) * x ----------------
// block 256 = 64 px x 4 co-groups(16); grid = 4*4096/64 = 256
__global__ void epilogue(const float* __restrict__ y2, const float* __restrict__ ww,
                         const float* __restrict__ wb, const float* __restrict__ am,
                         const float* __restrict__ x, float* __restrict__ out) {
    __shared__ float sy[64 * 33];
    __shared__ float sw[64 * 32];
    __shared__ float sb[64];
    int t = threadIdx.x;
    for (int l = t; l < 2048; l += 256) sw[l] = ww[l];
    if (t < 64) sb[t] = wb[t];
    int pxBase = blockIdx.x * 64;  // global pixel id (b*4096 + pix)
    for (int l = t; l < 2048; l += 256) {
        int p = l >> 5, c = l & 31;
        sy[p * 33 + c] = y2[(size_t)(pxBase + p) * 32 + c];
    }
    __syncthreads();
    int px = t & 63, cog = t >> 6;
    int b = pxBase >> 12;
    int pix = (pxBase & 4095) + px;
#pragma unroll
    for (int c16 = 0; c16 < 16; c16++) {
        int co = cog * 16 + c16;
        float a = sb[co];
#pragma unroll
        for (int c = 0; c < 32; c++) a += sw[co * 32 + c] * sy[px * 33 + c];
        int oidx = (b * 64 + co) * 4096 + pix;
        out[oidx] = (a + am[oidx]) * x[oidx];
    }
}

// ---------------- launch ----------------
extern "C" void kernel_launch(void* const* d_in, const int* in_sizes, int n_in,
                              void* d_out, int out_size) {
    (void)in_sizes; (void)n_in; (void)out_size;
    const float* x = (const float*)d_in[0];
    const float* d1w = (const float*)d_in[1];
    const float* d1b = (const float*)d_in[2];
    const float* d2w = (const float*)d_in[3];
    const float* d2b = (const float*)d_in[4];
    const float* d3w = (const float*)d_in[5];
    const float* d3b = (const float*)d_in[6];
    const float* gw = (const float*)d_in[7];
    const float* gb = (const float*)d_in[8];
    const float* thw = (const float*)d_in[9];
    const float* thb = (const float*)d_in[10];
    const float* phw = (const float*)d_in[11];
    const float* phb = (const float*)d_in[12];
    const float* www = (const float*)d_in[13];
    const float* wwb = (const float*)d_in[14];
    float* out = (float*)d_out;

    float *p_y1, *p_y2c, *p_y3, *p_am, *p_th, *p_ph, *p_g, *p_cs, *p_E, *p_y2a;
    cudaGetSymbolAddress((void**)&p_y1, g_y1);
    cudaGetSymbolAddress((void**)&p_y2c, g_y2c);
    cudaGetSymbolAddress((void**)&p_y3, g_y3);
    cudaGetSymbolAddress((void**)&p_am, g_am);
    cudaGetSymbolAddress((void**)&p_th, g_theta);
    cudaGetSymbolAddress((void**)&p_ph, g_phi);
    cudaGetSymbolAddress((void**)&p_g, g_gx);
    cudaGetSymbolAddress((void**)&p_cs, g_colsum);
    cudaGetSymbolAddress((void**)&p_E, g_E);
    cudaGetSymbolAddress((void**)&p_y2a, g_y2a);

    cudaMemsetAsync(p_cs, 0, 4 * 4096 * sizeof(float), 0);
    cudaMemsetAsync(p_y2a, 0, 4 * 4096 * 32 * sizeof(float), 0);

    // conv chain
    conv3x3_s2<<<128, 128>>>(x, p_y1, d1w, d1b, 64, 32, 1);
    conv3x3_s2<<<32, 128>>>(p_y1, p_y2c, d2w, d2b, 32, 16, 1);
    conv3x3_s2<<<8, 128>>>(p_y2c, p_y3, d3w, d3b, 16, 8, 0);

    // upsample + sigmoid gate
    upgate<<<4096, 256>>>(p_y3, x, p_am);

    // 1x1 projections (transposed outputs)
    proj1x1<<<64, 256>>>(p_am, thw, thb, phw, phb, gw, gb, p_th, p_ph, p_g);

    // E = exp(theta phi^T), column sums
    gemm1_exp<<<dim3(32, 32, 4), 256>>>(p_th, p_ph, p_E, p_cs);

    // g2 = g / colsum
    g2div<<<2048, 256>>>(p_g, p_cs);

    // y2 = E @ g2 (split-K)
    gemm2_av<<<dim3(32, 4, 4), 256>>>(p_E, p_g, p_y2a);

    // out = (W y2 + b + am) * x
    epilogue<<<256, 256>>>(p_y2a, www, wwb, p_am, x, out);
}

// round 2
// speedup vs baseline: 1.0005x; 1.0005x over previous
#include <cuda_runtime.h>
#include <cstdint>

// ---------------- scratch (device globals: allocation-free) ----------------
__device__ __align__(256) float g_y1[4 * 64 * 32 * 32];
__device__ __align__(256) float g_y2c[4 * 64 * 16 * 16];
__device__ __align__(256) float g_y3[4 * 64 * 8 * 8];
__device__ __align__(256) float g_am[4 * 64 * 4096];       // gated input, [b][c][hw]
__device__ __align__(256) float g_theta[4 * 4096 * 32];    // [b][i][c]
__device__ __align__(256) float g_phi[4 * 4096 * 32];      // [b][j][c]
__device__ __align__(256) float g_gx[4 * 4096 * 32];       // [b][j][c] (later /= colsum)
__device__ __align__(256) float g_colsum[4 * 4096];
__device__ __align__(256) float g_E[67108864];             // exp(f), [b][i][j] (268MB)
__device__ __align__(256) float g_y2a[4 * 4096 * 32];      // attention out, [b][i][c]

// ---------------- conv3x3 stride2 pad1, C=64 -> C=64 ----------------
// block: 128 threads = 32 pixels x 4 co-groups (16 co each)
__global__ void conv3x3_s2(const float* __restrict__ in, float* __restrict__ out,
                           const float* __restrict__ w, const float* __restrict__ bias,
                           int Hin, int Hout, int do_lrelu) {
    __shared__ float ws[16 * 64 * 9];  // [ci_local][co][9]  (36KB)
    int t = threadIdx.x;
    int pxl = t & 31, cog = t >> 5;
    int gpx = blockIdx.x * 32 + pxl;
    int hw2 = Hout * Hout;
    int b = gpx / hw2;
    int ohw = gpx - b * hw2;
    int oh = ohw / Hout, ow = ohw - oh * Hout;

    float acc[16];
#pragma unroll
    for (int c = 0; c < 16; c++) acc[c] = bias[cog * 16 + c];

    for (int cc = 0; cc < 64; cc += 16) {
        __syncthreads();
        for (int l = t; l < 16 * 64 * 9; l += 128) {
            int ci_l = l / 576;
            int rem = l - ci_l * 576;
            int co = rem / 9;
            int k = rem - co * 9;
            ws[l] = w[(co * 64 + cc + ci_l) * 9 + k];
        }
        __syncthreads();
        for (int ci_l = 0; ci_l < 16; ci_l++) {
            const float* inp = in + (b * 64 + cc + ci_l) * Hin * Hin;
            float v[9];
#pragma unroll
            for (int kh = 0; kh < 3; kh++)
#pragma unroll
                for (int kw = 0; kw < 3; kw++) {
                    int ih = 2 * oh - 1 + kh;
                    int iw = 2 * ow - 1 + kw;
                    bool ok = (ih >= 0) && (ih < Hin) && (iw >= 0) && (iw < Hin);
                    v[kh * 3 + kw] = ok ? inp[ih * Hin + iw] : 0.0f;
                }
            const float* wsp = ws + ci_l * 576 + cog * 16 * 9;
#pragma unroll
            for (int c = 0; c < 16; c++) {
#pragma unroll
                for (int k = 0; k < 9; k++) acc[c] += v[k] * wsp[c * 9 + k];
            }
        }
    }
    float* op = out + b * 64 * hw2 + ohw;
#pragma unroll
    for (int c = 0; c < 16; c++) {
        float vv = acc[c];
        if (do_lrelu) vv = (vv >= 0.0f) ? vv : 0.2f * vv;
        op[(cog * 16 + c) * hw2] = vv;
    }
}

// ---------------- bilinear 8->64 upsample + sigmoid gate ----------------
__global__ void upgate(const float* __restrict__ y3, const float* __restrict__ x,
                       float* __restrict__ am) {
    int idx = blockIdx.x * 256 + threadIdx.x;  // over 4*64*4096
    int hw = idx & 4095;
    int bc = idx >> 12;
    int h = hw >> 6, w = hw & 63;
    float sh = (h + 0.5f) * 0.125f - 0.5f;
    float sw = (w + 0.5f) * 0.125f - 0.5f;
    int h0 = (int)floorf(sh);
    int w0 = (int)floorf(sw);
    float fh = sh - (float)h0;
    float fw = sw - (float)w0;
    int h0c = min(max(h0, 0), 7), h1c = min(max(h0 + 1, 0), 7);
    int w0c = min(max(w0, 0), 7), w1c = min(max(w0 + 1, 0), 7);
    const float* yp = y3 + bc * 64;
    float v = (1.0f - fh) * ((1.0f - fw) * yp[h0c * 8 + w0c] + fw * yp[h0c * 8 + w1c]) +
              fh * ((1.0f - fw) * yp[h1c * 8 + w0c] + fw * yp[h1c * 8 + w1c]);
    float s = 1.0f / (1.0f + __expf(-v));
    am[idx] = s * x[idx];
}

// ---------------- 1x1 projections: am -> theta/phi/g, transposed [b][i][c] ----------------
__global__ void proj1x1(const float* __restrict__ am,
                        const float* __restrict__ thw, const float* __restrict__ thb,
                        const float* __restrict__ phw, const float* __restrict__ phb,
                        const float* __restrict__ gw, const float* __restrict__ gb,
                        float* __restrict__ theta, float* __restrict__ phi,
                        float* __restrict__ gx) {
    __shared__ float ws[3][32 * 64];
    __shared__ float bs[3][32];
    int t = threadIdx.x;  // 256
    for (int l = t; l < 3 * 2048; l += 256) {
        int o = l / 2048, r = l - o * 2048;
        const float* src = (o == 0) ? thw : ((o == 1) ? phw : gw);
        ws[o][r] = src[r];
    }
    if (t < 96) {
        int o = t / 32, c = t & 31;
        const float* src = (o == 0) ? thb : ((o == 1) ? phb : gb);
        bs[o][c] = src[c];
    }
    __syncthreads();
    int gi = blockIdx.x * 256 + t;  // over 4*4096
    int b = gi >> 12;
    int pix = gi & 4095;
    const float* ap = g_am + b * 64 * 4096 + pix;
    (void)am;
    for (int o = 0; o < 3; o++) {
        float acc[32];
#pragma unroll
        for (int c = 0; c < 32; c++) acc[c] = bs[o][c];
        for (int ci = 0; ci < 64; ci++) {
            float a = ap[ci * 4096];
#pragma unroll
            for (int c = 0; c < 32; c++) acc[c] += a * ws[o][c * 64 + ci];
        }
        float* outp = ((o == 0) ? theta : ((o == 1) ? phi : gx)) + (size_t)gi * 32;
#pragma unroll
        for (int c = 0; c < 32; c++) outp[c] = acc[c];
    }
}

// ---------------- GEMM1: E = exp(theta_t @ phi_t^T), + column sums ----------------
// grid (32 jTiles, 32 iTiles, 4 b), block 256, tile 128x128, micro 8x8 interleaved
__global__ __launch_bounds__(256, 2) void gemm1_exp(const float* __restrict__ theta,
                                                    const float* __restrict__ phi,
                                                    float* __restrict__ E,
                                                    float* __restrict__ colsum) {
    __shared__ float As[128 * 33];
    __shared__ float Bs[128 * 33];
    int t = threadIdx.x;
    int b = blockIdx.z;
    int iBase = blockIdx.y * 128, jBase = blockIdx.x * 128;
    const float4* Ag = (const float4*)(theta + ((size_t)b * 4096 + iBase) * 32);
    const float4* Bg = (const float4*)(phi + ((size_t)b * 4096 + jBase) * 32);
#pragma unroll
    for (int v = 0; v < 4; v++) {
        int l = t + v * 256;  // quad id in [0,1024)
        int row = l >> 3, q = l & 7;
        float4 d = Ag[l];
        float* s = &As[row * 33 + q * 4];
        s[0] = d.x; s[1] = d.y; s[2] = d.z; s[3] = d.w;
        float4 e = Bg[l];
        float* s2 = &Bs[row * 33 + q * 4];
        s2[0] = e.x; s2[1] = e.y; s2[2] = e.z; s2[3] = e.w;
    }
    __syncthreads();
    int tx = t & 15, ty = t >> 4;
    float acc[8][8];
#pragma unroll
    for (int u = 0; u < 8; u++)
#pragma unroll
        for (int v = 0; v < 8; v++) acc[u][v] = 0.0f;

#pragma unroll 8
    for (int k = 0; k < 32; k++) {
        float rA[8], rB[8];
#pragma unroll
        for (int u = 0; u < 8; u++) rA[u] = As[(ty + u * 16) * 33 + k];
#pragma unroll
        for (int v = 0; v < 8; v++) rB[v] = Bs[(tx + v * 16) * 33 + k];
#pragma unroll
        for (int u = 0; u < 8; u++)
#pragma unroll
            for (int v = 0; v < 8; v++) acc[u][v] += rA[u] * rB[v];
    }

    float csum[8];
#pragma unroll
    for (int v = 0; v < 8; v++) csum[v] = 0.0f;
#pragma unroll
    for (int u = 0; u < 8; u++) {
        float* Erow = E + ((size_t)(b * 4096 + iBase + ty + u * 16)) * 4096 + jBase;
#pragma unroll
        for (int v = 0; v < 8; v++) {
            float e = __expf(acc[u][v]);
            csum[v] += e;
            Erow[tx + v * 16] = e;
        }
    }
    __syncthreads();
    float* red = As;  // reuse: [16 ty][128 cols]
#pragma unroll
    for (int v = 0; v < 8; v++) red[ty * 128 + tx + v * 16] = csum[v];
    __syncthreads();
    if (t < 128) {
        float s = 0.0f;
#pragma unroll
        for (int r = 0; r < 16; r++) s += red[r * 128 + t];
        atomicAdd(&colsum[b * 4096 + jBase + t], s);
    }
}

// ---------------- g2 = g / colsum[j] ----------------
__global__ void g2div(float* __restrict__ gx, const float* __restrict__ colsum) {
    int idx = blockIdx.x * 256 + threadIdx.x;  // 4*4096*32
    gx[idx] = gx[idx] / colsum[idx >> 5];
}

// ---------------- GEMM2: y2[b,i,c] += sum_j E[i,j] * g2[j,c]  (split-K atomic) ----------------
// grid (32 iTiles, 4 jSplit, 4 b), block 256 = (tx:8 c-groups x4) x (ty:32 i-groups x4)
__global__ __launch_bounds__(256, 2) void gemm2_av(const float* __restrict__ E,
                                                   const float* __restrict__ g2,
                                                   float* __restrict__ y2) {
    __shared__ float Es[128 * 65];
    __shared__ float Gs[64 * 33];
    int t = threadIdx.x;
    int tx = t & 7, ty = t >> 3;
    int b = blockIdx.z;
    int iBase = blockIdx.x * 128;
    int jStart = blockIdx.y * 1024;
    float acc[4][4];
#pragma unroll
    for (int u = 0; u < 4; u++)
#pragma unroll
        for (int v = 0; v < 4; v++) acc[u][v] = 0.0f;

    for (int j0 = jStart; j0 < jStart + 1024; j0 += 64) {
        __syncthreads();
        // load E tile 128x64
#pragma unroll
        for (int v = 0; v < 8; v++) {
            int l = t + v * 256;  // quad in [0,2048)
            int row = l >> 4, q = l & 15;
            float4 d = *(const float4*)(E + ((size_t)(b * 4096 + iBase + row)) * 4096 + j0 + q * 4);
            float* s = &Es[row * 65 + q * 4];
            s[0] = d.x; s[1] = d.y; s[2] = d.z; s[3] = d.w;
        }
        // load g2 tile 64x32
#pragma unroll
        for (int v = 0; v < 2; v++) {
            int l = t + v * 256;  // quad in [0,512)
            int row = l >> 3, q = l & 7;
            float4 d = *(const float4*)(g2 + (size_t)(b * 4096 + j0 + row) * 32 + q * 4);
            float* s = &Gs[row * 33 + q * 4];
            s[0] = d.x; s[1] = d.y; s[2] = d.z; s[3] = d.w;
        }
        __syncthreads();
#pragma unroll 8
        for (int jj = 0; jj < 64; jj++) {
            float rA[4], rB[4];
#pragma unroll
            for (int u = 0; u < 4; u++) rA[u] = Es[(ty + u * 32) * 65 + jj];
#pragma unroll
            for (int v = 0; v < 4; v++) rB[v] = Gs[jj * 33 + tx + v * 8];
#pragma unroll
            for (int u = 0; u < 4; u++)
#pragma unroll
                for (int v = 0; v < 4; v++) acc[u][v] += rA[u] * rB[v];
        }
    }
#pragma unroll
    for (int u = 0; u < 4; u++)
#pragma unroll
        for (int v = 0; v < 4; v++)
            atomicAdd(&y2[(size_t)(b * 4096 + iBase + ty + u * 32) * 32 + tx + v * 8],
                      acc[u][v]);
}

// ---------------- epilogue: out = (W@y2 + wb + am) * x ----------------
// block 256 = 64 px x 4 co-groups(16); grid = 4*4096/64 = 256
__global__ void epilogue(const float* __restrict__ y2, const float* __restrict__ ww,
                         const float* __restrict__ wb, const float* __restrict__ am,
                         const float* __restrict__ x, float* __restrict__ out) {
    __shared__ float sy[64 * 33];
    __shared__ float sw[64 * 32];
    __shared__ float sb[64];
    int t = threadIdx.x;
    for (int l = t; l < 2048; l += 256) sw[l] = ww[l];
    if (t < 64) sb[t] = wb[t];
    int pxBase = blockIdx.x * 64;  // global pixel id (b*4096 + pix)
    for (int l = t; l < 2048; l += 256) {
        int p = l >> 5, c = l & 31;
        sy[p * 33 + c] = y2[(size_t)(pxBase + p) * 32 + c];
    }
    __syncthreads();
    int px = t & 63, cog = t >> 6;
    int b = pxBase >> 12;
    int pix = (pxBase & 4095) + px;
#pragma unroll
    for (int c16 = 0; c16 < 16; c16++) {
        int co = cog * 16 + c16;
        float a = sb[co];
#pragma unroll
        for (int c = 0; c < 32; c++) a += sw[co * 32 + c] * sy[px * 33 + c];
        int oidx = (b * 64 + co) * 4096 + pix;
        out[oidx] = (a + am[oidx]) * x[oidx];
    }
}

// ---------------- launch ----------------
extern "C" void kernel_launch(void* const* d_in, const int* in_sizes, int n_in,
                              void* d_out, int out_size) {
    (void)in_sizes; (void)n_in; (void)out_size;
    const float* x = (const float*)d_in[0];
    const float* d1w = (const float*)d_in[1];
    const float* d1b = (const float*)d_in[2];
    const float* d2w = (const float*)d_in[3];
    const float* d2b = (const float*)d_in[4];
    const float* d3w = (const float*)d_in[5];
    const float* d3b = (const float*)d_in[6];
    const float* gw = (const float*)d_in[7];
    const float* gb = (const float*)d_in[8];
    const float* thw = (const float*)d_in[9];
    const float* thb = (const float*)d_in[10];
    const float* phw = (const float*)d_in[11];
    const float* phb = (const float*)d_in[12];
    const float* www = (const float*)d_in[13];
    const float* wwb = (const float*)d_in[14];
    float* out = (float*)d_out;

    float *p_y1, *p_y2c, *p_y3, *p_am, *p_th, *p_ph, *p_g, *p_cs, *p_E, *p_y2a;
    cudaGetSymbolAddress((void**)&p_y1, g_y1);
    cudaGetSymbolAddress((void**)&p_y2c, g_y2c);
    cudaGetSymbolAddress((void**)&p_y3, g_y3);
    cudaGetSymbolAddress((void**)&p_am, g_am);
    cudaGetSymbolAddress((void**)&p_th, g_theta);
    cudaGetSymbolAddress((void**)&p_ph, g_phi);
    cudaGetSymbolAddress((void**)&p_g, g_gx);
    cudaGetSymbolAddress((void**)&p_cs, g_colsum);
    cudaGetSymbolAddress((void**)&p_E, g_E);
    cudaGetSymbolAddress((void**)&p_y2a, g_y2a);

    cudaMemsetAsync(p_cs, 0, 4 * 4096 * sizeof(float), 0);
    cudaMemsetAsync(p_y2a, 0, 4 * 4096 * 32 * sizeof(float), 0);

    // conv chain
    conv3x3_s2<<<128, 128>>>(x, p_y1, d1w, d1b, 64, 32, 1);
    conv3x3_s2<<<32, 128>>>(p_y1, p_y2c, d2w, d2b, 32, 16, 1);
    conv3x3_s2<<<8, 128>>>(p_y2c, p_y3, d3w, d3b, 16, 8, 0);

    // upsample + sigmoid gate
    upgate<<<4096, 256>>>(p_y3, x, p_am);

    // 1x1 projections (transposed outputs)
    proj1x1<<<64, 256>>>(p_am, thw, thb, phw, phb, gw, gb, p_th, p_ph, p_g);

    // E = exp(theta phi^T), column sums
    gemm1_exp<<<dim3(32, 32, 4), 256>>>(p_th, p_ph, p_E, p_cs);

    // g2 = g / colsum
    g2div<<<2048, 256>>>(p_g, p_cs);

    // y2 = E @ g2 (split-K)
    gemm2_av<<<dim3(32, 4, 4), 256>>>(p_E, p_g, p_y2a);

    // out = (W y2 + b + am) * x
    epilogue<<<256, 256>>>(p_y2a, www, wwb, p_am, x, out);
}

// round 5
// speedup vs baseline: 1.6932x; 1.6924x over previous
#include <cuda_runtime.h>
#include <cuda_bf16.h>
#include <cstdint>

// ==================== device scratch (allocation-free) ====================
__device__ __align__(256) float g_y1[4 * 64 * 32 * 32];
__device__ __align__(256) float g_y2c[4 * 64 * 16 * 16];
__device__ __align__(256) float g_y3[4 * 64 * 8 * 8];
__device__ __align__(256) float g_am[4 * 64 * 4096];            // gated input [b][c][hw]
__device__ __align__(256) __nv_bfloat16 g_thb[4 * 4096 * 32];   // theta bf16 [b][i][c]
__device__ __align__(256) __nv_bfloat16 g_phb[4 * 4096 * 32];   // phi   bf16 [b][j][c]
__device__ __align__(256) float g_g[4 * 4096 * 32];             // g fp32 [b][j][c]
__device__ __align__(256) float g_colsum[4 * 4096];
__device__ __align__(256) __nv_bfloat16 g_E[67108864];          // exp(f) bf16 [b][i][j]
__device__ __align__(256) __nv_bfloat16 g_g2t[4 * 32 * 4096];   // g/colsum bf16 [b][c][j]
__device__ __align__(256) float g_y2a[4 * 4096 * 32];           // attn out fp32 [b][i][c]

// ==================== helpers (portable sm_80+ PTX only) ====================
__device__ __forceinline__ uint32_t smem_u32(const void* p) {
    uint32_t a;
    asm("{ .reg .u64 t; cvta.to.shared.u64 t, %1; cvt.u32.u64 %0, t; }" : "=r"(a) : "l"(p));
    return a;
}
__device__ __forceinline__ uint32_t pack_bf16x2(float lo, float hi) {
    uint32_t r;
    asm("cvt.rn.bf16x2.f32 %0, %1, %2;" : "=r"(r) : "f"(hi), "f"(lo));
    return r;
}
#define LDM_X4(r0, r1, r2, r3, a) \
    asm volatile("ldmatrix.sync.aligned.m8n8.x4.shared.b16 {%0,%1,%2,%3}, [%4];" \
                 : "=r"(r0), "=r"(r1), "=r"(r2), "=r"(r3) : "r"(a))
#define LDM_X2(r0, r1, a) \
    asm volatile("ldmatrix.sync.aligned.m8n8.x2.shared.b16 {%0,%1}, [%2];" \
                 : "=r"(r0), "=r"(r1) : "r"(a))
#define MMA16816(c0, c1, c2, c3, a0, a1, a2, a3, b0, b1) \
    asm volatile("mma.sync.aligned.m16n8k16.row.col.f32.bf16.bf16.f32 " \
                 "{%0,%1,%2,%3}, {%4,%5,%6,%7}, {%8,%9}, {%0,%1,%2,%3};" \
                 : "+f"(c0), "+f"(c1), "+f"(c2), "+f"(c3) \
                 : "r"(a0), "r"(a1), "r"(a2), "r"(a3), "r"(b0), "r"(b1))
#define CP_ASYNC16(dst, src) \
    asm volatile("cp.async.cg.shared.global [%0], [%1], 16;" :: "r"(dst), "l"(src) : "memory")
#define CP_COMMIT() asm volatile("cp.async.commit_group;" ::: "memory")
#define CP_WAIT1() asm volatile("cp.async.wait_group 1;" ::: "memory")

// ==================== conv3x3 stride2 pad1, C=64 -> C=64 ====================
__global__ void conv3x3_s2(const float* __restrict__ in, float* __restrict__ out,
                           const float* __restrict__ w, const float* __restrict__ bias,
                           int Hin, int Hout, int do_lrelu) {
    __shared__ float ws[16 * 64 * 9];
    int t = threadIdx.x;
    int pxl = t & 31, cog = t >> 5;
    int gpx = blockIdx.x * 32 + pxl;
    int hw2 = Hout * Hout;
    int b = gpx / hw2;
    int ohw = gpx - b * hw2;
    int oh = ohw / Hout, ow = ohw - oh * Hout;

    float acc[16];
#pragma unroll
    for (int c = 0; c < 16; c++) acc[c] = bias[cog * 16 + c];

    for (int cc = 0; cc < 64; cc += 16) {
        __syncthreads();
        for (int l = t; l < 16 * 64 * 9; l += 128) {
            int ci_l = l / 576;
            int rem = l - ci_l * 576;
            int co = rem / 9;
            int k = rem - co * 9;
            ws[l] = w[(co * 64 + cc + ci_l) * 9 + k];
        }
        __syncthreads();
        for (int ci_l = 0; ci_l < 16; ci_l++) {
            const float* inp = in + (b * 64 + cc + ci_l) * Hin * Hin;
            float v[9];
#pragma unroll
            for (int kh = 0; kh < 3; kh++)
#pragma unroll
                for (int kw = 0; kw < 3; kw++) {
                    int ih = 2 * oh - 1 + kh;
                    int iw = 2 * ow - 1 + kw;
                    bool ok = (ih >= 0) && (ih < Hin) && (iw >= 0) && (iw < Hin);
                    v[kh * 3 + kw] = ok ? inp[ih * Hin + iw] : 0.0f;
                }
            const float* wsp = ws + ci_l * 576 + cog * 16 * 9;
#pragma unroll
            for (int c = 0; c < 16; c++)
#pragma unroll
                for (int k = 0; k < 9; k++) acc[c] += v[k] * wsp[c * 9 + k];
        }
    }
    float* op = out + b * 64 * hw2 + ohw;
#pragma unroll
    for (int c = 0; c < 16; c++) {
        float vv = acc[c];
        if (do_lrelu) vv = (vv >= 0.0f) ? vv : 0.2f * vv;
        op[(cog * 16 + c) * hw2] = vv;
    }
}

// ==================== bilinear 8->64 upsample + sigmoid gate ====================
__global__ void upgate(const float* __restrict__ y3, const float* __restrict__ x,
                       float* __restrict__ am) {
    int idx = blockIdx.x * 256 + threadIdx.x;
    int hw = idx & 4095;
    int bc = idx >> 12;
    int h = hw >> 6, w = hw & 63;
    float sh = (h + 0.5f) * 0.125f - 0.5f;
    float sw = (w + 0.5f) * 0.125f - 0.5f;
    int h0 = (int)floorf(sh);
    int w0 = (int)floorf(sw);
    float fh = sh - (float)h0;
    float fw = sw - (float)w0;
    int h0c = min(max(h0, 0), 7), h1c = min(max(h0 + 1, 0), 7);
    int w0c = min(max(w0, 0), 7), w1c = min(max(w0 + 1, 0), 7);
    const float* yp = y3 + bc * 64;
    float v = (1.0f - fh) * ((1.0f - fw) * yp[h0c * 8 + w0c] + fw * yp[h0c * 8 + w1c]) +
              fh * ((1.0f - fw) * yp[h1c * 8 + w0c] + fw * yp[h1c * 8 + w1c]);
    float s = 1.0f / (1.0f + __expf(-v));
    am[idx] = s * x[idx];
}

// ==================== 1x1 projections: am -> theta/phi bf16 + g fp32 ====================
__global__ void proj1x1(const float* __restrict__ am,
                        const float* __restrict__ thw, const float* __restrict__ thb,
                        const float* __restrict__ phw, const float* __restrict__ phb,
                        const float* __restrict__ gw, const float* __restrict__ gb,
                        __nv_bfloat16* __restrict__ thetab, __nv_bfloat16* __restrict__ phib,
                        float* __restrict__ gx) {
    __shared__ float ws[3][32 * 64];
    __shared__ float bs[3][32];
    int t = threadIdx.x;
    for (int l = t; l < 3 * 2048; l += 256) {
        int o = l / 2048, r = l - o * 2048;
        const float* src = (o == 0) ? thw : ((o == 1) ? phw : gw);
        ws[o][r] = src[r];
    }
    if (t < 96) {
        int o = t / 32, c = t & 31;
        const float* src = (o == 0) ? thb : ((o == 1) ? phb : gb);
        bs[o][c] = src[c];
    }
    __syncthreads();
    int gi = blockIdx.x * 256 + t;
    int b = gi >> 12;
    const float* ap = am + (size_t)b * 64 * 4096 + (gi & 4095);
    for (int o = 0; o < 3; o++) {
        float acc[32];
#pragma unroll
        for (int c = 0; c < 32; c++) acc[c] = bs[o][c];
        for (int ci = 0; ci < 64; ci++) {
            float a = ap[ci * 4096];
#pragma unroll
            for (int c = 0; c < 32; c++) acc[c] += a * ws[o][c * 64 + ci];
        }
        if (o < 2) {
            uint32_t* outp = (uint32_t*)((o == 0) ? thetab : phib) + (size_t)gi * 16;
#pragma unroll
            for (int p = 0; p < 16; p++) outp[p] = pack_bf16x2(acc[2 * p], acc[2 * p + 1]);
        } else {
            float* outp = gx + (size_t)gi * 32;
#pragma unroll
            for (int p = 0; p < 8; p++)
                *(float4*)(outp + p * 4) = make_float4(acc[4 * p], acc[4 * p + 1], acc[4 * p + 2], acc[4 * p + 3]);
        }
    }
}

// ==================== GEMM1 (HMMA): f = theta @ phi^T ; E = exp(f) bf16 ; colsum over i ====
// grid (32 jT, 32 iT, 4 b), 256 thr. Warp grid 2(m=i) x 4(n=j); warp tile 64x32.
__global__ __launch_bounds__(256) void gemm1_mma(const __nv_bfloat16* __restrict__ thetab,
                                                 const __nv_bfloat16* __restrict__ phib,
                                                 __nv_bfloat16* __restrict__ E,
                                                 float* __restrict__ colsum) {
    __shared__ __align__(16) unsigned char sm[36864];  // tiles: 2x10240; staging: 128*288
    uint32_t smb = smem_u32(sm);
    const int TS = 0, PS = 10240;  // theta rows (i), phi rows (j); stride 80B (K=32 bf16 = 64B + 16 pad)
    int t = threadIdx.x, wid = t >> 5, lane = t & 31;
    int b = blockIdx.z;
    int i0 = blockIdx.y * 128, j0 = blockIdx.x * 128;

    // load tiles: 128 rows x 4 x 16B each
#pragma unroll
    for (int v = 0; v < 2; v++) {
        int idx = t + v * 256;  // [0,512)
        int row = idx >> 2, c16 = idx & 3;
        float4 da = *(const float4*)((const char*)thetab + ((size_t)((b << 12) + i0 + row)) * 64 + c16 * 16);
        *(float4*)(sm + TS + row * 80 + c16 * 16) = da;
        float4 db = *(const float4*)((const char*)phib + ((size_t)((b << 12) + j0 + row)) * 64 + c16 * 16);
        *(float4*)(sm + PS + row * 80 + c16 * 16) = db;
    }
    __syncthreads();

    int wm = wid >> 2, wn = wid & 3;  // warp row (i), warp col (j)
    float acc[4][4][4];
#pragma unroll
    for (int mt = 0; mt < 4; mt++)
#pragma unroll
        for (int nt = 0; nt < 4; nt++)
#pragma unroll
            for (int r = 0; r < 4; r++) acc[mt][nt][r] = 0.0f;

#pragma unroll
    for (int kt = 0; kt < 2; kt++) {
        // B fragments (phi): 4 ntiles
        uint32_t bf[4][2];
#pragma unroll
        for (int nt = 0; nt < 4; nt++) {
            int idx = lane & 15;
            int nrow = wn * 32 + nt * 8 + (idx & 7);
            uint32_t a = smb + PS + nrow * 80 + kt * 32 + ((idx >> 3) & 1) * 16;
            LDM_X2(bf[nt][0], bf[nt][1], a);
        }
#pragma unroll
        for (int mt = 0; mt < 4; mt++) {
            uint32_t af[4];
            int mrow = wm * 64 + mt * 16 + (lane & 15);
            uint32_t a = smb + TS + mrow * 80 + kt * 32 + (lane >> 4) * 16;
            LDM_X4(af[0], af[1], af[2], af[3], a);
#pragma unroll
            for (int nt = 0; nt < 4; nt++)
                MMA16816(acc[mt][nt][0], acc[mt][nt][1], acc[mt][nt][2], acc[mt][nt][3],
                         af[0], af[1], af[2], af[3], bf[nt][0], bf[nt][1]);
        }
    }
    __syncthreads();  // tiles no longer needed; reuse sm as staging

    // exp + stage + column partial sums. Staging: [i_local][j_local] bf16, stride 288B.
    uint32_t* stg = (uint32_t*)sm;
    int q = lane & 3, gq = lane >> 2;
    float csum[4][2];
#pragma unroll
    for (int nt = 0; nt < 4; nt++) { csum[nt][0] = 0.0f; csum[nt][1] = 0.0f; }
#pragma unroll
    for (int mt = 0; mt < 4; mt++) {
        int row = wm * 64 + mt * 16 + gq;
#pragma unroll
        for (int nt = 0; nt < 4; nt++) {
            int col = wn * 32 + nt * 8 + q * 2;
            float e0 = __expf(acc[mt][nt][0]);
            float e1 = __expf(acc[mt][nt][1]);
            float e2 = __expf(acc[mt][nt][2]);
            float e3 = __expf(acc[mt][nt][3]);
            csum[nt][0] += e0 + e2;
            csum[nt][1] += e1 + e3;
            stg[(row * 288 + col * 2) >> 2] = pack_bf16x2(e0, e1);
            stg[((row + 8) * 288 + col * 2) >> 2] = pack_bf16x2(e2, e3);
        }
    }
    // reduce over lane-group bits (rows), then atomicAdd per column
#pragma unroll
    for (int nt = 0; nt < 4; nt++)
#pragma unroll
        for (int s = 0; s < 2; s++) {
            float v = csum[nt][s];
            v += __shfl_xor_sync(0xFFFFFFFF, v, 4);
            v += __shfl_xor_sync(0xFFFFFFFF, v, 8);
            v += __shfl_xor_sync(0xFFFFFFFF, v, 16);
            if (gq == 0)
                atomicAdd(&colsum[b * 4096 + j0 + wn * 32 + nt * 8 + q * 2 + s], v);
        }
    __syncthreads();

    // drain: thread (row=t>>1, half=t&1) writes 8 x 16B chunks (chunk idx 2c+half)
    int row = t >> 1, half = t & 1;
    char* ebase = (char*)E + (((size_t)((b << 12) + i0 + row)) * 4096 + (size_t)j0) * 2;
    const char* sbase = (const char*)sm + row * 288;
#pragma unroll
    for (int c = 0; c < 8; c++) {
        int m = 2 * c + half;
        uint4 v = *(const uint4*)(sbase + m * 16);
        *(uint4*)(ebase + m * 16) = v;
    }
}

// ==================== g2t[b][c][j] = bf16( g[b][j][c] / colsum[b][j] ) ====================
__global__ void g2div_t(const float* __restrict__ g, const float* __restrict__ colsum,
                        __nv_bfloat16* __restrict__ g2t) {
    __shared__ float sg[256 * 33];
    int t = threadIdx.x;
    int b = blockIdx.y;
    int j0 = blockIdx.x * 256;
#pragma unroll
    for (int v = 0; v < 8; v++) {
        int idx = t + v * 256;
        int row = idx >> 3, c4 = idx & 7;
        float4 d = *(const float4*)(g + ((size_t)((b << 12) + j0 + row)) * 32 + c4 * 4);
        float* s = &sg[row * 33 + c4 * 4];
        s[0] = d.x; s[1] = d.y; s[2] = d.z; s[3] = d.w;
    }
    __syncthreads();
    float inv = 1.0f / colsum[(b << 12) + j0 + t];
#pragma unroll
    for (int c = 0; c < 32; c++)
        g2t[((size_t)(b * 32 + c)) * 4096 + j0 + t] = __float2bfloat16(sg[t * 33 + c] * inv);
}

// ==================== GEMM2 (HMMA): y2 += E @ g2t^T, split-K=4, 2-stage cp.async ========
// grid (32 iT, 4 ksplit, 4 b), 256 thr. Warp w handles rows w*16..w*16+15, all 32 cols.
__global__ __launch_bounds__(256) void gemm2_mma(const __nv_bfloat16* __restrict__ E,
                                                 const __nv_bfloat16* __restrict__ g2t,
                                                 float* __restrict__ y2) {
    __shared__ __align__(16) unsigned char sm[2 * 23040];  // per stage: A 128*144, B 32*144
    uint32_t smb = smem_u32(sm);
    int t = threadIdx.x, wid = t >> 5, lane = t & 31;
    int b = blockIdx.z;
    int i0 = blockIdx.x * 128;
    int kbase = blockIdx.y * 1024;
    size_t rowbase = (size_t)((b << 12) + i0);

    auto load_stage = [&](int s, int chunk) {
        int j0 = kbase + chunk * 64;
        uint32_t sA = smb + s * 23040;
        uint32_t sB = sA + 18432;
#pragma unroll
        for (int v = 0; v < 4; v++) {
            int idx = t + v * 256;  // [0,1024): 128 rows x 8 chunks
            int row = idx >> 3, c16 = idx & 7;
            const char* src = (const char*)E + ((rowbase + row) * 4096 + (size_t)j0) * 2 + c16 * 16;
            CP_ASYNC16(sA + row * 144 + c16 * 16, src);
        }
        {
            int row = t >> 3, c16 = t & 7;  // 32 rows x 8 chunks
            const char* src = (const char*)g2t + (((size_t)(b * 32 + row)) * 4096 + (size_t)j0) * 2 + c16 * 16;
            CP_ASYNC16(sB + row * 144 + c16 * 16, src);
        }
        CP_COMMIT();
    };

    float acc[4][4];
#pragma unroll
    for (int nt = 0; nt < 4; nt++)
#pragma unroll
        for (int r = 0; r < 4; r++) acc[nt][r] = 0.0f;

    load_stage(0, 0);
    load_stage(1, 1);

    for (int c = 0; c < 16; c++) {
        int s = c & 1;
        CP_WAIT1();
        __syncthreads();
        uint32_t sA = smb + s * 23040;
        uint32_t sB = sA + 18432;
#pragma unroll
        for (int kt = 0; kt < 4; kt++) {
            uint32_t af[4];
            {
                int row = wid * 16 + (lane & 15);
                uint32_t a = sA + row * 144 + kt * 32 + (lane >> 4) * 16;
                LDM_X4(af[0], af[1], af[2], af[3], a);
            }
#pragma unroll
            for (int nt = 0; nt < 4; nt++) {
                uint32_t b0, b1;
                int idx = lane & 15;
                int nrow = nt * 8 + (idx & 7);
                uint32_t a = sB + nrow * 144 + kt * 32 + ((idx >> 3) & 1) * 16;
                LDM_X2(b0, b1, a);
                MMA16816(acc[nt][0], acc[nt][1], acc[nt][2], acc[nt][3],
                         af[0], af[1], af[2], af[3], b0, b1);
            }
        }
        __syncthreads();
        if (c + 2 < 16) load_stage(s, c + 2);
        else CP_COMMIT();
    }

    // finish: fp32 atomics into y2 [b][i][c]
    int q = lane & 3, gq = lane >> 2;
#pragma unroll
    for (int nt = 0; nt < 4; nt++) {
        int col = nt * 8 + q * 2;
        size_t r0 = (rowbase + wid * 16 + gq) * 32;
        size_t r1 = (rowbase + wid * 16 + gq + 8) * 32;
        atomicAdd(&y2[r0 + col], acc[nt][0]);
        atomicAdd(&y2[r0 + col + 1], acc[nt][1]);
        atomicAdd(&y2[r1 + col], acc[nt][2]);
        atomicAdd(&y2[r1 + col + 1], acc[nt][3]);
    }
}

// ==================== epilogue: out = (W@y2 + wb + am) * x ====================
__global__ void epilogue(const float* __restrict__ y2, const float* __restrict__ ww,
                         const float* __restrict__ wb, const float* __restrict__ am,
                         const float* __restrict__ x, float* __restrict__ out) {
    __shared__ float sy[64 * 33];
    __shared__ float sw[64 * 32];
    __shared__ float sb[64];
    int t = threadIdx.x;
    for (int l = t; l < 2048; l += 256) sw[l] = ww[l];
    if (t < 64) sb[t] = wb[t];
    int pxBase = blockIdx.x * 64;
    for (int l = t; l < 2048; l += 256) {
        int p = l >> 5, c = l & 31;
        sy[p * 33 + c] = y2[(size_t)(pxBase + p) * 32 + c];
    }
    __syncthreads();
    int px = t & 63, cog = t >> 6;
    int b = pxBase >> 12;
    int pix = (pxBase & 4095) + px;
#pragma unroll
    for (int c16 = 0; c16 < 16; c16++) {
        int co = cog * 16 + c16;
        float a = sb[co];
#pragma unroll
        for (int c = 0; c < 32; c++) a += sw[co * 32 + c] * sy[px * 33 + c];
        int oidx = (b * 64 + co) * 4096 + pix;
        out[oidx] = (a + am[oidx]) * x[oidx];
    }
}

// ==================== launch ====================
extern "C" void kernel_launch(void* const* d_in, const int* in_sizes, int n_in,
                              void* d_out, int out_size) {
    (void)in_sizes; (void)n_in; (void)out_size;
    const float* x = (const float*)d_in[0];
    const float* d1w = (const float*)d_in[1];
    const float* d1b = (const float*)d_in[2];
    const float* d2w = (const float*)d_in[3];
    const float* d2b = (const float*)d_in[4];
    const float* d3w = (const float*)d_in[5];
    const float* d3b = (const float*)d_in[6];
    const float* gw = (const float*)d_in[7];
    const float* gb = (const float*)d_in[8];
    const float* thw = (const float*)d_in[9];
    const float* thb = (const float*)d_in[10];
    const float* phw = (const float*)d_in[11];
    const float* phb = (const float*)d_in[12];
    const float* www = (const float*)d_in[13];
    const float* wwb = (const float*)d_in[14];
    float* out = (float*)d_out;

    float *p_y1, *p_y2c, *p_y3, *p_am, *p_g, *p_cs, *p_y2a;
    __nv_bfloat16 *p_th, *p_ph, *p_E, *p_g2t;
    cudaGetSymbolAddress((void**)&p_y1, g_y1);
    cudaGetSymbolAddress((void**)&p_y2c, g_y2c);
    cudaGetSymbolAddress((void**)&p_y3, g_y3);
    cudaGetSymbolAddress((void**)&p_am, g_am);
    cudaGetSymbolAddress((void**)&p_th, g_thb);
    cudaGetSymbolAddress((void**)&p_ph, g_phb);
    cudaGetSymbolAddress((void**)&p_g, g_g);
    cudaGetSymbolAddress((void**)&p_cs, g_colsum);
    cudaGetSymbolAddress((void**)&p_E, g_E);
    cudaGetSymbolAddress((void**)&p_g2t, g_g2t);
    cudaGetSymbolAddress((void**)&p_y2a, g_y2a);

    cudaMemsetAsync(p_cs, 0, 4 * 4096 * sizeof(float), 0);
    cudaMemsetAsync(p_y2a, 0, 4 * 4096 * 32 * sizeof(float), 0);

    conv3x3_s2<<<128, 128>>>(x, p_y1, d1w, d1b, 64, 32, 1);
    conv3x3_s2<<<32, 128>>>(p_y1, p_y2c, d2w, d2b, 32, 16, 1);
    conv3x3_s2<<<8, 128>>>(p_y2c, p_y3, d3w, d3b, 16, 8, 0);

    upgate<<<4096, 256>>>(p_y3, x, p_am);

    proj1x1<<<64, 256>>>(p_am, thw, thb, phw, phb, gw, gb, p_th, p_ph, p_g);

    gemm1_mma<<<dim3(32, 32, 4), 256>>>(p_th, p_ph, p_E, p_cs);

    g2div_t<<<dim3(16, 4), 256>>>(p_g, p_cs, p_g2t);

    gemm2_mma<<<dim3(32, 4, 4), 256>>>(p_E, p_g2t, p_y2a);

    epilogue<<<256, 256>>>(p_y2a, www, wwb, p_am, x, out);
}

// round 6
// speedup vs baseline: 1.9575x; 1.1561x over previous
#include <cuda_runtime.h>
#include <cuda_bf16.h>
#include <cstdint>

// ==================== device scratch (allocation-free) ====================
__device__ __align__(256) float g_y1[4 * 64 * 32 * 32];
__device__ __align__(256) float g_y2c[4 * 64 * 16 * 16];
__device__ __align__(256) float g_y3[4 * 64 * 8 * 8];
__device__ __align__(256) float g_am[4 * 64 * 4096];            // gated input [b][c][hw]
__device__ __align__(256) __nv_bfloat16 g_thb[4 * 4096 * 32];   // theta*log2e bf16 [b][i][c]
__device__ __align__(256) __nv_bfloat16 g_phb[4 * 4096 * 32];   // phi bf16 [b][j][c]
__device__ __align__(256) float g_g[4 * 4096 * 32];             // g fp32 [b][j][c]
__device__ __align__(256) __nv_bfloat16 g_g2t[4 * 32 * 4096];   // g/colsum bf16 [b][c][j]
__device__ __align__(256) float g_y2a[4 * 4096 * 32];           // attn out fp32 [b][i][c]

// ==================== helpers (portable sm_80+ PTX only) ====================
__device__ __forceinline__ uint32_t smem_u32(const void* p) {
    uint32_t a;
    asm("{ .reg .u64 t; cvta.to.shared.u64 t, %1; cvt.u32.u64 %0, t; }" : "=r"(a) : "l"(p));
    return a;
}
__device__ __forceinline__ uint32_t pack_bf16x2(float lo, float hi) {
    uint32_t r;
    asm("cvt.rn.bf16x2.f32 %0, %1, %2;" : "=r"(r) : "f"(hi), "f"(lo));
    return r;
}
__device__ __forceinline__ float ex2f(float x) {
    float r;
    asm("ex2.approx.f32 %0, %1;" : "=f"(r) : "f"(x));
    return r;
}
#define LDM_X4(r0, r1, r2, r3, a) \
    asm volatile("ldmatrix.sync.aligned.m8n8.x4.shared.b16 {%0,%1,%2,%3}, [%4];" \
                 : "=r"(r0), "=r"(r1), "=r"(r2), "=r"(r3) : "r"(a))
#define LDM_X2(r0, r1, a) \
    asm volatile("ldmatrix.sync.aligned.m8n8.x2.shared.b16 {%0,%1}, [%2];" \
                 : "=r"(r0), "=r"(r1) : "r"(a))
#define MMA16816(c0, c1, c2, c3, a0, a1, a2, a3, b0, b1) \
    asm volatile("mma.sync.aligned.m16n8k16.row.col.f32.bf16.bf16.f32 " \
                 "{%0,%1,%2,%3}, {%4,%5,%6,%7}, {%8,%9}, {%0,%1,%2,%3};" \
                 : "+f"(c0), "+f"(c1), "+f"(c2), "+f"(c3) \
                 : "r"(a0), "r"(a1), "r"(a2), "r"(a3), "r"(b0), "r"(b1))
#define CP_ASYNC16(dst, src) \
    asm volatile("cp.async.cg.shared.global [%0], [%1], 16;" :: "r"(dst), "l"(src) : "memory")
#define CP_COMMIT() asm volatile("cp.async.commit_group;" ::: "memory")
#define CP_WAIT1() asm volatile("cp.async.wait_group 1;" ::: "memory")

// ==================== conv3x3 stride2 pad1, C=64 -> C=64 ====================
__global__ void conv3x3_s2(const float* __restrict__ in, float* __restrict__ out,
                           const float* __restrict__ w, const float* __restrict__ bias,
                           int Hin, int Hout, int do_lrelu) {
    __shared__ float ws[16 * 64 * 9];
    int t = threadIdx.x;
    int pxl = t & 31, cog = t >> 5;
    int gpx = blockIdx.x * 32 + pxl;
    int hw2 = Hout * Hout;
    int b = gpx / hw2;
    int ohw = gpx - b * hw2;
    int oh = ohw / Hout, ow = ohw - oh * Hout;

    float acc[16];
#pragma unroll
    for (int c = 0; c < 16; c++) acc[c] = bias[cog * 16 + c];

    for (int cc = 0; cc < 64; cc += 16) {
        __syncthreads();
        for (int l = t; l < 16 * 64 * 9; l += 128) {
            int ci_l = l / 576;
            int rem = l - ci_l * 576;
            int co = rem / 9;
            int k = rem - co * 9;
            ws[l] = w[(co * 64 + cc + ci_l) * 9 + k];
        }
        __syncthreads();
        for (int ci_l = 0; ci_l < 16; ci_l++) {
            const float* inp = in + (b * 64 + cc + ci_l) * Hin * Hin;
            float v[9];
#pragma unroll
            for (int kh = 0; kh < 3; kh++)
#pragma unroll
                for (int kw = 0; kw < 3; kw++) {
                    int ih = 2 * oh - 1 + kh;
                    int iw = 2 * ow - 1 + kw;
                    bool ok = (ih >= 0) && (ih < Hin) && (iw >= 0) && (iw < Hin);
                    v[kh * 3 + kw] = ok ? inp[ih * Hin + iw] : 0.0f;
                }
            const float* wsp = ws + ci_l * 576 + cog * 16 * 9;
#pragma unroll
            for (int c = 0; c < 16; c++)
#pragma unroll
                for (int k = 0; k < 9; k++) acc[c] += v[k] * wsp[c * 9 + k];
        }
    }
    float* op = out + b * 64 * hw2 + ohw;
#pragma unroll
    for (int c = 0; c < 16; c++) {
        float vv = acc[c];
        if (do_lrelu) vv = (vv >= 0.0f) ? vv : 0.2f * vv;
        op[(cog * 16 + c) * hw2] = vv;
    }
}

// ==================== bilinear 8->64 upsample + sigmoid gate ====================
__global__ void upgate(const float* __restrict__ y3, const float* __restrict__ x,
                       float* __restrict__ am) {
    int idx = blockIdx.x * 256 + threadIdx.x;
    int hw = idx & 4095;
    int bc = idx >> 12;
    int h = hw >> 6, w = hw & 63;
    float sh = (h + 0.5f) * 0.125f - 0.5f;
    float sw = (w + 0.5f) * 0.125f - 0.5f;
    int h0 = (int)floorf(sh);
    int w0 = (int)floorf(sw);
    float fh = sh - (float)h0;
    float fw = sw - (float)w0;
    int h0c = min(max(h0, 0), 7), h1c = min(max(h0 + 1, 0), 7);
    int w0c = min(max(w0, 0), 7), w1c = min(max(w0 + 1, 0), 7);
    const float* yp = y3 + bc * 64;
    float v = (1.0f - fh) * ((1.0f - fw) * yp[h0c * 8 + w0c] + fw * yp[h0c * 8 + w1c]) +
              fh * ((1.0f - fw) * yp[h1c * 8 + w0c] + fw * yp[h1c * 8 + w1c]);
    float s = 1.0f / (1.0f + __expf(-v));
    am[idx] = s * x[idx];
}

// ==================== 1x1 projections: am -> theta(*log2e)/phi bf16 + g fp32 ============
__global__ void proj1x1(const float* __restrict__ am,
                        const float* __restrict__ thw, const float* __restrict__ thb,
                        const float* __restrict__ phw, const float* __restrict__ phb,
                        const float* __restrict__ gw, const float* __restrict__ gb,
                        __nv_bfloat16* __restrict__ thetab, __nv_bfloat16* __restrict__ phib,
                        float* __restrict__ gx) {
    __shared__ float ws[3][32 * 64];
    __shared__ float bs[3][32];
    int t = threadIdx.x;
    for (int l = t; l < 3 * 2048; l += 256) {
        int o = l / 2048, r = l - o * 2048;
        const float* src = (o == 0) ? thw : ((o == 1) ? phw : gw);
        ws[o][r] = src[r];
    }
    if (t < 96) {
        int o = t / 32, c = t & 31;
        const float* src = (o == 0) ? thb : ((o == 1) ? phb : gb);
        bs[o][c] = src[c];
    }
    __syncthreads();
    int gi = blockIdx.x * 256 + t;
    int b = gi >> 12;
    const float* ap = am + (size_t)b * 64 * 4096 + (gi & 4095);
    for (int o = 0; o < 3; o++) {
        float acc[32];
#pragma unroll
        for (int c = 0; c < 32; c++) acc[c] = bs[o][c];
        for (int ci = 0; ci < 64; ci++) {
            float a = ap[ci * 4096];
#pragma unroll
            for (int c = 0; c < 32; c++) acc[c] += a * ws[o][c * 64 + ci];
        }
        if (o == 0) {
            // fold log2(e) into theta so exp(f) == exp2(theta' . phi)
            uint32_t* outp = (uint32_t*)thetab + (size_t)gi * 16;
#pragma unroll
            for (int p = 0; p < 16; p++)
                outp[p] = pack_bf16x2(acc[2 * p] * 1.4426950408889634f,
                                      acc[2 * p + 1] * 1.4426950408889634f);
        } else if (o == 1) {
            uint32_t* outp = (uint32_t*)phib + (size_t)gi * 16;
#pragma unroll
            for (int p = 0; p < 16; p++) outp[p] = pack_bf16x2(acc[2 * p], acc[2 * p + 1]);
        } else {
            float* outp = gx + (size_t)gi * 32;
#pragma unroll
            for (int p = 0; p < 8; p++)
                *(float4*)(outp + p * 4) = make_float4(acc[4 * p], acc[4 * p + 1], acc[4 * p + 2], acc[4 * p + 3]);
        }
    }
}

// ==================== pass1: colsum over i for 128 j columns; emit g2t = g/colsum =========
// grid (32 jT, 4 b), 256 thr (8 warps x 16 j rows). Streams theta chunks (i), 2-stage cp.async.
__global__ __launch_bounds__(256) void attn_pass1(const __nv_bfloat16* __restrict__ thetab,
                                                  const __nv_bfloat16* __restrict__ phib,
                                                  const float* __restrict__ g,
                                                  __nv_bfloat16* __restrict__ g2t) {
    __shared__ __align__(16) unsigned char sm[31232];
    // layout: sphi[0..10240), sth0[10240..20480), sth1[20480..30720), sinv[30720..31232)
    uint32_t smb = smem_u32(sm);
    const int SPHI = 0, STH0 = 10240, STH1 = 20480, SINV = 30720;
    int t = threadIdx.x, wid = t >> 5, lane = t & 31;
    int b = blockIdx.y;
    int j0 = blockIdx.x * 128;

    // load phi tile (rows j0..j0+127, 64B each) into sphi, stride 80
#pragma unroll
    for (int v = 0; v < 2; v++) {
        int idx = t + v * 256;
        int row = idx >> 2, c16 = idx & 3;
        float4 d = *(const float4*)((const char*)phib + ((size_t)((b << 12) + j0 + row)) * 64 + c16 * 16);
        *(float4*)(sm + SPHI + row * 80 + c16 * 16) = d;
    }
    __syncthreads();

    // A fragments: phi rows wid*16..wid*16+15 (m = j), 2 k-tiles
    uint32_t af[2][4];
#pragma unroll
    for (int kt = 0; kt < 2; kt++) {
        uint32_t a = smb + SPHI + (wid * 16 + (lane & 15)) * 80 + kt * 32 + (lane >> 4) * 16;
        LDM_X4(af[kt][0], af[kt][1], af[kt][2], af[kt][3], a);
    }

    auto load_th = [&](uint32_t soff, int chunk) {
#pragma unroll
        for (int v = 0; v < 2; v++) {
            int idx = t + v * 256;
            int row = idx >> 2, c16 = idx & 3;
            const char* src = (const char*)thetab + ((size_t)((b << 12) + chunk * 128 + row)) * 64 + c16 * 16;
            CP_ASYNC16(smb + soff + row * 80 + c16 * 16, src);
        }
        CP_COMMIT();
    };
    load_th(STH0, 0);
    load_th(STH1, 1);

    float cs0 = 0.0f, cs1 = 0.0f;
    for (int chunk = 0; chunk < 32; chunk++) {
        uint32_t soff = (chunk & 1) ? STH1 : STH0;
        CP_WAIT1();
        __syncthreads();
#pragma unroll
        for (int nt = 0; nt < 16; nt++) {
            int idx = lane & 15;
            uint32_t bb = smb + soff + (nt * 8 + (idx & 7)) * 80 + ((idx >> 3) & 1) * 16;
            uint32_t b0, b1, b2, b3;
            LDM_X2(b0, b1, bb);
            LDM_X2(b2, b3, bb + 32);
            float c0 = 0.0f, c1 = 0.0f, c2 = 0.0f, c3 = 0.0f;
            MMA16816(c0, c1, c2, c3, af[0][0], af[0][1], af[0][2], af[0][3], b0, b1);
            MMA16816(c0, c1, c2, c3, af[1][0], af[1][1], af[1][2], af[1][3], b2, b3);
            cs0 += ex2f(c0) + ex2f(c1);
            cs1 += ex2f(c2) + ex2f(c3);
        }
        __syncthreads();
        if (chunk + 2 < 32) load_th(soff, chunk + 2);
        else CP_COMMIT();
    }

    // reduce over q lanes -> full row sums (rows j = wid*16+gq, +8)
    cs0 += __shfl_xor_sync(0xFFFFFFFF, cs0, 1);
    cs0 += __shfl_xor_sync(0xFFFFFFFF, cs0, 2);
    cs1 += __shfl_xor_sync(0xFFFFFFFF, cs1, 1);
    cs1 += __shfl_xor_sync(0xFFFFFFFF, cs1, 2);
    float* sinv = (float*)(sm + SINV);
    if ((lane & 3) == 0) {
        sinv[wid * 16 + (lane >> 2)] = 1.0f / cs0;
        sinv[wid * 16 + 8 + (lane >> 2)] = 1.0f / cs1;
    }
    __syncthreads();

    // g2t tail: read g rows j0..j0+127, scale, transpose-stage (reuse STH0), write bf16
    __nv_bfloat16* sgt = (__nv_bfloat16*)(sm + STH0);  // [c][j_local], stride 136 elems (272B)
    {
        int r = t >> 1, half = t & 1;
        const float* gp = g + ((size_t)((b << 12) + j0 + r)) * 32 + half * 16;
        float inv = sinv[r];
#pragma unroll
        for (int c = 0; c < 16; c++)
            sgt[(half * 16 + c) * 136 + r] = __float2bfloat16(gp[c] * inv);
    }
    __syncthreads();
#pragma unroll
    for (int v = 0; v < 2; v++) {
        int idx = t + v * 256;  // [0,512): 32 c-rows x 16 chunks of 16B
        int c = idx >> 4, c16 = idx & 15;
        uint4 d = *(const uint4*)((const char*)sgt + c * 272 + c16 * 16);
        *(uint4*)((char*)g2t + (((size_t)(b * 32 + c)) * 4096 + (size_t)j0) * 2 + c16 * 16) = d;
    }
}

// ==================== pass2: y2[i,c] = sum_j exp2(f') * g2t  (fused, no E) ================
// grid (32 iT, 4 b), 256 thr (8 warps x 16 i rows). Streams phi + g2t chunks (j).
__global__ __launch_bounds__(256) void attn_pass2(const __nv_bfloat16* __restrict__ thetab,
                                                  const __nv_bfloat16* __restrict__ phib,
                                                  const __nv_bfloat16* __restrict__ g2t,
                                                  float* __restrict__ y2) {
    __shared__ __align__(16) unsigned char sm[48128];
    // layout: sth[0..10240), sphi0[10240..20480), sphi1[20480..30720), sg0[30720..39424), sg1[39424..48128)
    uint32_t smb = smem_u32(sm);
    const int STH = 0, SPHI0 = 10240, SPHI1 = 20480, SG0 = 30720, SG1 = 39424;
    int t = threadIdx.x, wid = t >> 5, lane = t & 31;
    int b = blockIdx.y;
    int i0 = blockIdx.x * 128;

    // load theta tile (rows i0..i0+127) into sth, stride 80
#pragma unroll
    for (int v = 0; v < 2; v++) {
        int idx = t + v * 256;
        int row = idx >> 2, c16 = idx & 3;
        float4 d = *(const float4*)((const char*)thetab + ((size_t)((b << 12) + i0 + row)) * 64 + c16 * 16);
        *(float4*)(sm + STH + row * 80 + c16 * 16) = d;
    }
    __syncthreads();

    // A fragments: theta rows wid*16.. (m = i), 2 k-tiles
    uint32_t af[2][4];
#pragma unroll
    for (int kt = 0; kt < 2; kt++) {
        uint32_t a = smb + STH + (wid * 16 + (lane & 15)) * 80 + kt * 32 + (lane >> 4) * 16;
        LDM_X4(af[kt][0], af[kt][1], af[kt][2], af[kt][3], a);
    }

    auto load_chunk = [&](uint32_t sphi, uint32_t sg, int chunk) {
#pragma unroll
        for (int v = 0; v < 2; v++) {
            int idx = t + v * 256;
            int row = idx >> 2, c16 = idx & 3;
            const char* src = (const char*)phib + ((size_t)((b << 12) + chunk * 128 + row)) * 64 + c16 * 16;
            CP_ASYNC16(smb + sphi + row * 80 + c16 * 16, src);
        }
#pragma unroll
        for (int v = 0; v < 2; v++) {
            int idx = t + v * 256;  // [0,512): 32 rows x 16 chunks of 16B
            int row = idx >> 4, c16 = idx & 15;
            const char* src = (const char*)g2t + (((size_t)(b * 32 + row)) * 4096 + (size_t)(chunk * 128)) * 2 + c16 * 16;
            CP_ASYNC16(smb + sg + row * 272 + c16 * 16, src);
        }
        CP_COMMIT();
    };
    load_chunk(SPHI0, SG0, 0);
    load_chunk(SPHI1, SG1, 1);

    float y2acc[4][4];
#pragma unroll
    for (int cn = 0; cn < 4; cn++)
#pragma unroll
        for (int r = 0; r < 4; r++) y2acc[cn][r] = 0.0f;

    for (int chunk = 0; chunk < 32; chunk++) {
        uint32_t sphi = (chunk & 1) ? SPHI1 : SPHI0;
        uint32_t sg = (chunk & 1) ? SG1 : SG0;
        CP_WAIT1();
        __syncthreads();
#pragma unroll
        for (int p = 0; p < 8; p++) {  // j 16-wide groups: ntiles 2p, 2p+1
            float c[2][4];
#pragma unroll
            for (int half = 0; half < 2; half++) {
                int nt = 2 * p + half;
                int idx = lane & 15;
                uint32_t bb = smb + sphi + (nt * 8 + (idx & 7)) * 80 + ((idx >> 3) & 1) * 16;
                uint32_t b0, b1, b2, b3;
                LDM_X2(b0, b1, bb);
                LDM_X2(b2, b3, bb + 32);
                c[half][0] = 0.0f; c[half][1] = 0.0f; c[half][2] = 0.0f; c[half][3] = 0.0f;
                MMA16816(c[half][0], c[half][1], c[half][2], c[half][3],
                         af[0][0], af[0][1], af[0][2], af[0][3], b0, b1);
                MMA16816(c[half][0], c[half][1], c[half][2], c[half][3],
                         af[1][0], af[1][1], af[1][2], af[1][3], b2, b3);
            }
            // exp2 + repack C->A fragments (16 i x 16 j)
            uint32_t pa[4];
            pa[0] = pack_bf16x2(ex2f(c[0][0]), ex2f(c[0][1]));
            pa[1] = pack_bf16x2(ex2f(c[0][2]), ex2f(c[0][3]));
            pa[2] = pack_bf16x2(ex2f(c[1][0]), ex2f(c[1][1]));
            pa[3] = pack_bf16x2(ex2f(c[1][2]), ex2f(c[1][3]));
            // PV: k-tile p (16 j), B = g2t (n = c)
#pragma unroll
            for (int cn = 0; cn < 4; cn++) {
                int idx = lane & 15;
                uint32_t bb = smb + sg + (cn * 8 + (idx & 7)) * 272 + p * 32 + ((idx >> 3) & 1) * 16;
                uint32_t b0, b1;
                LDM_X2(b0, b1, bb);
                MMA16816(y2acc[cn][0], y2acc[cn][1], y2acc[cn][2], y2acc[cn][3],
                         pa[0], pa[1], pa[2], pa[3], b0, b1);
            }
        }
        __syncthreads();
        if (chunk + 2 < 32) load_chunk(sphi, sg, chunk + 2);
        else CP_COMMIT();
    }

    // store y2 (direct, no atomics)
    int q = lane & 3, gq = lane >> 2;
#pragma unroll
    for (int cn = 0; cn < 4; cn++) {
        int col = cn * 8 + q * 2;
        size_t r0 = ((size_t)((b << 12) + i0 + wid * 16 + gq)) * 32;
        size_t r1 = ((size_t)((b << 12) + i0 + wid * 16 + gq + 8)) * 32;
        *(float2*)&y2[r0 + col] = make_float2(y2acc[cn][0], y2acc[cn][1]);
        *(float2*)&y2[r1 + col] = make_float2(y2acc[cn][2], y2acc[cn][3]);
    }
}

// ==================== epilogue: out = (W@y2 + wb + am) * x ====================
__global__ void epilogue(const float* __restrict__ y2, const float* __restrict__ ww,
                         const float* __restrict__ wb, const float* __restrict__ am,
                         const float* __restrict__ x, float* __restrict__ out) {
    __shared__ float sy[64 * 33];
    __shared__ float sw[64 * 32];
    __shared__ float sb[64];
    int t = threadIdx.x;
    for (int l = t; l < 2048; l += 256) sw[l] = ww[l];
    if (t < 64) sb[t] = wb[t];
    int pxBase = blockIdx.x * 64;
    for (int l = t; l < 2048; l += 256) {
        int p = l >> 5, c = l & 31;
        sy[p * 33 + c] = y2[(size_t)(pxBase + p) * 32 + c];
    }
    __syncthreads();
    int px = t & 63, cog = t >> 6;
    int b = pxBase >> 12;
    int pix = (pxBase & 4095) + px;
#pragma unroll
    for (int c16 = 0; c16 < 16; c16++) {
        int co = cog * 16 + c16;
        float a = sb[co];
#pragma unroll
        for (int c = 0; c < 32; c++) a += sw[co * 32 + c] * sy[px * 33 + c];
        int oidx = (b * 64 + co) * 4096 + pix;
        out[oidx] = (a + am[oidx]) * x[oidx];
    }
}

// ==================== launch ====================
extern "C" void kernel_launch(void* const* d_in, const int* in_sizes, int n_in,
                              void* d_out, int out_size) {
    (void)in_sizes; (void)n_in; (void)out_size;
    const float* x = (const float*)d_in[0];
    const float* d1w = (const float*)d_in[1];
    const float* d1b = (const float*)d_in[2];
    const float* d2w = (const float*)d_in[3];
    const float* d2b = (const float*)d_in[4];
    const float* d3w = (const float*)d_in[5];
    const float* d3b = (const float*)d_in[6];
    const float* gw = (const float*)d_in[7];
    const float* gb = (const float*)d_in[8];
    const float* thw = (const float*)d_in[9];
    const float* thb = (const float*)d_in[10];
    const float* phw = (const float*)d_in[11];
    const float* phb = (const float*)d_in[12];
    const float* www = (const float*)d_in[13];
    const float* wwb = (const float*)d_in[14];
    float* out = (float*)d_out;

    float *p_y1, *p_y2c, *p_y3, *p_am, *p_g, *p_y2a;
    __nv_bfloat16 *p_th, *p_ph, *p_g2t;
    cudaGetSymbolAddress((void**)&p_y1, g_y1);
    cudaGetSymbolAddress((void**)&p_y2c, g_y2c);
    cudaGetSymbolAddress((void**)&p_y3, g_y3);
    cudaGetSymbolAddress((void**)&p_am, g_am);
    cudaGetSymbolAddress((void**)&p_th, g_thb);
    cudaGetSymbolAddress((void**)&p_ph, g_phb);
    cudaGetSymbolAddress((void**)&p_g, g_g);
    cudaGetSymbolAddress((void**)&p_g2t, g_g2t);
    cudaGetSymbolAddress((void**)&p_y2a, g_y2a);

    // launch order fixed so ncu (-s 5 -c 1) profiles attn_pass1 (6th launch)
    conv3x3_s2<<<128, 128>>>(x, p_y1, d1w, d1b, 64, 32, 1);          // 0
    conv3x3_s2<<<32, 128>>>(p_y1, p_y2c, d2w, d2b, 32, 16, 1);       // 1
    conv3x3_s2<<<8, 128>>>(p_y2c, p_y3, d3w, d3b, 16, 8, 0);         // 2
    upgate<<<4096, 256>>>(p_y3, x, p_am);                            // 3
    proj1x1<<<64, 256>>>(p_am, thw, thb, phw, phb, gw, gb, p_th, p_ph, p_g);  // 4
    attn_pass1<<<dim3(32, 4), 256>>>(p_th, p_ph, p_g, p_g2t);        // 5 <- profiled
    attn_pass2<<<dim3(32, 4), 256>>>(p_th, p_ph, p_g2t, p_y2a);      // 6
    epilogue<<<256, 256>>>(p_y2a, www, wwb, p_am, x, out);           // 7
}

// round 7
// speedup vs baseline: 2.6242x; 1.3406x over previous
#include <cuda_runtime.h>
#include <cuda_bf16.h>
#include <cstdint>

// ==================== device scratch (allocation-free) ====================
__device__ __align__(256) float g_y1[4 * 64 * 32 * 32];
__device__ __align__(256) float g_y2c[4 * 64 * 16 * 16];
__device__ __align__(256) float g_y3[4 * 64 * 8 * 8];
__device__ __align__(256) float g_am[4 * 64 * 4096];            // gated input [b][c][hw]
__device__ __align__(256) __nv_bfloat16 g_thb[4 * 4096 * 32];   // theta*log2e bf16 [b][i][c]
__device__ __align__(256) __nv_bfloat16 g_phb[4 * 4096 * 32];   // phi bf16 [b][j][c]
__device__ __align__(256) float g_g[4 * 4096 * 32];             // g fp32 [b][j][c]
__device__ __align__(256) __nv_bfloat16 g_g2t[4 * 32 * 4096];   // g/colsum bf16 [b][c][j]
__device__ __align__(256) float g_y2a[4 * 4096 * 32];           // attn out fp32 [b][i][c]

// ==================== helpers (portable sm_80+ PTX only) ====================
__device__ __forceinline__ uint32_t smem_u32(const void* p) {
    uint32_t a;
    asm("{ .reg .u64 t; cvta.to.shared.u64 t, %1; cvt.u32.u64 %0, t; }" : "=r"(a) : "l"(p));
    return a;
}
__device__ __forceinline__ uint32_t pack_bf16x2(float lo, float hi) {
    uint32_t r;
    asm("cvt.rn.bf16x2.f32 %0, %1, %2;" : "=r"(r) : "f"(hi), "f"(lo));
    return r;
}
__device__ __forceinline__ float ex2f(float x) {
    float r;
    asm("ex2.approx.f32 %0, %1;" : "=f"(r) : "f"(x));
    return r;
}
#define LDM_X4(r0, r1, r2, r3, a) \
    asm volatile("ldmatrix.sync.aligned.m8n8.x4.shared.b16 {%0,%1,%2,%3}, [%4];" \
                 : "=r"(r0), "=r"(r1), "=r"(r2), "=r"(r3) : "r"(a))
#define MMA16816(c0, c1, c2, c3, a0, a1, a2, a3, b0, b1) \
    asm volatile("mma.sync.aligned.m16n8k16.row.col.f32.bf16.bf16.f32 " \
                 "{%0,%1,%2,%3}, {%4,%5,%6,%7}, {%8,%9}, {%0,%1,%2,%3};" \
                 : "+f"(c0), "+f"(c1), "+f"(c2), "+f"(c3) \
                 : "r"(a0), "r"(a1), "r"(a2), "r"(a3), "r"(b0), "r"(b1))
#define CP_ASYNC16(dst, src) \
    asm volatile("cp.async.cg.shared.global [%0], [%1], 16;" :: "r"(dst), "l"(src) : "memory")
#define CP_COMMIT() asm volatile("cp.async.commit_group;" ::: "memory")
#define CP_WAIT1() asm volatile("cp.async.wait_group 1;" ::: "memory")

// ==================== conv3x3 stride2 pad1, C=64 -> C=64 (templated geometry) =========
template <int PX, int NCO>
__global__ void conv3x3_s2(const float* __restrict__ in, float* __restrict__ out,
                           const float* __restrict__ w, const float* __restrict__ bias,
                           int Hin, int Hout, int do_lrelu) {
    __shared__ float ws[16 * 64 * 9];
    const int NT = PX * (64 / NCO);
    int t = threadIdx.x;
    int pxl = t % PX, cog = t / PX;
    int gpx = blockIdx.x * PX + pxl;
    int hw2 = Hout * Hout;
    int b = gpx / hw2;
    int ohw = gpx - b * hw2;
    int oh = ohw / Hout, ow = ohw - oh * Hout;

    float acc[NCO];
#pragma unroll
    for (int c = 0; c < NCO; c++) acc[c] = bias[cog * NCO + c];

    for (int cc = 0; cc < 64; cc += 16) {
        __syncthreads();
        for (int l = t; l < 16 * 64 * 9; l += NT) {
            int ci_l = l / 576;
            int rem = l - ci_l * 576;
            int co = rem / 9;
            int k = rem - co * 9;
            ws[l] = w[(co * 64 + cc + ci_l) * 9 + k];
        }
        __syncthreads();
        for (int ci_l = 0; ci_l < 16; ci_l++) {
            const float* inp = in + (b * 64 + cc + ci_l) * Hin * Hin;
            float v[9];
#pragma unroll
            for (int kh = 0; kh < 3; kh++)
#pragma unroll
                for (int kw = 0; kw < 3; kw++) {
                    int ih = 2 * oh - 1 + kh;
                    int iw = 2 * ow - 1 + kw;
                    bool ok = (ih >= 0) && (ih < Hin) && (iw >= 0) && (iw < Hin);
                    v[kh * 3 + kw] = ok ? inp[ih * Hin + iw] : 0.0f;
                }
            const float* wsp = ws + ci_l * 576 + cog * NCO * 9;
#pragma unroll
            for (int c = 0; c < NCO; c++)
#pragma unroll
                for (int k = 0; k < 9; k++) acc[c] += v[k] * wsp[c * 9 + k];
        }
    }
    float* op = out + b * 64 * hw2 + ohw;
#pragma unroll
    for (int c = 0; c < NCO; c++) {
        float vv = acc[c];
        if (do_lrelu) vv = (vv >= 0.0f) ? vv : 0.2f * vv;
        op[(cog * NCO + c) * hw2] = vv;
    }
}

// ==================== amproj: fused upsample+sigmoid-gate + three 1x1 projections ======
// grid 128 (128 px each), 384 thr. Dynamic smem: wst 24576 | ams 33280 | bss 384.
__global__ __launch_bounds__(384) void amproj(
    const float* __restrict__ y3, const float* __restrict__ x,
    const float* __restrict__ thw, const float* __restrict__ thb,
    const float* __restrict__ phw, const float* __restrict__ phb,
    const float* __restrict__ gw, const float* __restrict__ gb,
    float* __restrict__ am, __nv_bfloat16* __restrict__ thetab,
    __nv_bfloat16* __restrict__ phib, float* __restrict__ gx) {
    extern __shared__ __align__(16) float dynsm[];
    float* wst = dynsm;                 // [o][ci][c] : 3*64*32
    float* ams = dynsm + 6144;          // [px][ci] stride 65 : 128*65
    float* bss = dynsm + 6144 + 8320;   // [o][c] : 96
    int t = threadIdx.x;
    // transpose-load projection weights
    for (int l = t; l < 6144; l += 384) {
        int o = l / 2048;
        int r = l - o * 2048;
        int c = r >> 6, ci = r & 63;
        const float* src = (o == 0) ? thw : ((o == 1) ? phw : gw);
        wst[o * 2048 + ci * 32 + c] = src[c * 64 + ci];
    }
    if (t < 96) {
        int o = t / 32, c = t & 31;
        const float* src = (o == 0) ? thb : ((o == 1) ? phb : gb);
        bss[o * 32 + c] = src[c];
    }
    int pxBase = blockIdx.x * 128;
    int b = pxBase >> 12;
    int pix0 = pxBase & 4095;
    // phase 1: am for 128 px x 64 ci
    for (int l = t; l < 8192; l += 384) {
        int ci = l >> 7, px = l & 127;
        int pix = pix0 + px;
        int h = pix >> 6, w = pix & 63;
        float sh = (h + 0.5f) * 0.125f - 0.5f;
        float sw = (w + 0.5f) * 0.125f - 0.5f;
        int h0 = (int)floorf(sh);
        int w0 = (int)floorf(sw);
        float fh = sh - (float)h0;
        float fw = sw - (float)w0;
        int h0c = min(max(h0, 0), 7), h1c = min(max(h0 + 1, 0), 7);
        int w0c = min(max(w0, 0), 7), w1c = min(max(w0 + 1, 0), 7);
        const float* yp = y3 + (b * 64 + ci) * 64;
        float v = (1.0f - fh) * ((1.0f - fw) * yp[h0c * 8 + w0c] + fw * yp[h0c * 8 + w1c]) +
                  fh * ((1.0f - fw) * yp[h1c * 8 + w0c] + fw * yp[h1c * 8 + w1c]);
        float s = 1.0f / (1.0f + __expf(-v));
        float a = s * x[(size_t)(b * 64 + ci) * 4096 + pix];
        ams[px * 65 + ci] = a;
        am[(size_t)(b * 64 + ci) * 4096 + pix] = a;
    }
    __syncthreads();
    // phase 2: 3 o-groups x 128 px
    int o = t >> 7, px = t & 127;
    const float* wso = wst + o * 2048;
    float acc[32];
#pragma unroll
    for (int c = 0; c < 32; c++) acc[c] = bss[o * 32 + c];
    const float* ap = ams + px * 65;
#pragma unroll 8
    for (int ci = 0; ci < 64; ci++) {
        float a = ap[ci];
        const float* wrow = wso + ci * 32;
#pragma unroll
        for (int c = 0; c < 32; c++) acc[c] += a * wrow[c];
    }
    size_t gi = (size_t)(pxBase + px);
    if (o == 0) {
        uint32_t* outp = (uint32_t*)thetab + gi * 16;
#pragma unroll
        for (int p = 0; p < 16; p++)
            outp[p] = pack_bf16x2(acc[2 * p] * 1.4426950408889634f,
                                  acc[2 * p + 1] * 1.4426950408889634f);
    } else if (o == 1) {
        uint32_t* outp = (uint32_t*)phib + gi * 16;
#pragma unroll
        for (int p = 0; p < 16; p++) outp[p] = pack_bf16x2(acc[2 * p], acc[2 * p + 1]);
    } else {
        float* outp = gx + gi * 32;
#pragma unroll
        for (int p = 0; p < 8; p++)
            *(float4*)(outp + p * 4) = make_float4(acc[4 * p], acc[4 * p + 1], acc[4 * p + 2], acc[4 * p + 3]);
    }
}

// ==================== pass1: colsum over i for 64 j columns; emit g2t = g/colsum ========
// grid (64 jT, 4 b), 128 thr (4 warps x 16 j). Streams theta chunks (128 i), 2-stage.
__global__ __launch_bounds__(128) void attn_pass1(const __nv_bfloat16* __restrict__ thetab,
                                                  const __nv_bfloat16* __restrict__ phib,
                                                  const float* __restrict__ g,
                                                  __nv_bfloat16* __restrict__ g2t) {
    __shared__ __align__(16) unsigned char sm[25856];
    // SPHI[0..5120) STH0[5120..15360) STH1[15360..25600) SINV[25600..25856)
    uint32_t smb = smem_u32(sm);
    const int SPHI = 0, STH0 = 5120, STH1 = 15360, SINV = 25600;
    int t = threadIdx.x, wid = t >> 5, lane = t & 31;
    int b = blockIdx.y;
    int j0 = blockIdx.x * 64;

    // load phi tile (64 rows x 64B), stride 80
#pragma unroll
    for (int v = 0; v < 2; v++) {
        int idx = t + v * 128;  // [0,256)
        int row = idx >> 2, c16 = idx & 3;
        float4 d = *(const float4*)((const char*)phib + ((size_t)((b << 12) + j0 + row)) * 64 + c16 * 16);
        *(float4*)(sm + SPHI + row * 80 + c16 * 16) = d;
    }
    __syncthreads();

    uint32_t af[2][4];
#pragma unroll
    for (int kt = 0; kt < 2; kt++) {
        uint32_t a = smb + SPHI + (wid * 16 + (lane & 15)) * 80 + kt * 32 + (lane >> 4) * 16;
        LDM_X4(af[kt][0], af[kt][1], af[kt][2], af[kt][3], a);
    }

    auto load_th = [&](uint32_t soff, int chunk) {
#pragma unroll
        for (int v = 0; v < 4; v++) {
            int idx = t + v * 128;  // [0,512)
            int row = idx >> 2, c16 = idx & 3;
            const char* src = (const char*)thetab + ((size_t)((b << 12) + chunk * 128 + row)) * 64 + c16 * 16;
            CP_ASYNC16(smb + soff + row * 80 + c16 * 16, src);
        }
        CP_COMMIT();
    };
    load_th(STH0, 0);
    load_th(STH1, 1);

    float cs0 = 0.0f, cs1 = 0.0f;
    for (int chunk = 0; chunk < 32; chunk++) {
        uint32_t soff = (chunk & 1) ? STH1 : STH0;
        CP_WAIT1();
        __syncthreads();
#pragma unroll
        for (int nt = 0; nt < 16; nt++) {
            uint32_t b0, b1, b2, b3;
            // one x4: lane-group g -> byte g*16 (kt0 b0,b1 then kt1 b0,b1)
            LDM_X4(b0, b1, b2, b3, smb + soff + (nt * 8 + (lane & 7)) * 80 + (lane >> 3) * 16);
            float c0 = 0.0f, c1 = 0.0f, c2 = 0.0f, c3 = 0.0f;
            MMA16816(c0, c1, c2, c3, af[0][0], af[0][1], af[0][2], af[0][3], b0, b1);
            MMA16816(c0, c1, c2, c3, af[1][0], af[1][1], af[1][2], af[1][3], b2, b3);
            cs0 += ex2f(c0) + ex2f(c1);
            cs1 += ex2f(c2) + ex2f(c3);
        }
        __syncthreads();
        if (chunk + 2 < 32) load_th(soff, chunk + 2);
        else CP_COMMIT();
    }

    cs0 += __shfl_xor_sync(0xFFFFFFFF, cs0, 1);
    cs0 += __shfl_xor_sync(0xFFFFFFFF, cs0, 2);
    cs1 += __shfl_xor_sync(0xFFFFFFFF, cs1, 1);
    cs1 += __shfl_xor_sync(0xFFFFFFFF, cs1, 2);
    float* sinv = (float*)(sm + SINV);
    if ((lane & 3) == 0) {
        sinv[wid * 16 + (lane >> 2)] = 1.0f / cs0;
        sinv[wid * 16 + 8 + (lane >> 2)] = 1.0f / cs1;
    }
    __syncthreads();

    // tail: g2t[c][j0..j0+63] = g[j][c]/colsum[j]; stage [c][j] stride 144B
    __nv_bfloat16* sgt = (__nv_bfloat16*)(sm + SPHI);
    {
        int r = t >> 1, half = t & 1;  // r: 64 j rows
        const float* gp = g + ((size_t)((b << 12) + j0 + r)) * 32 + half * 16;
        float inv = sinv[r];
#pragma unroll
        for (int c = 0; c < 16; c++)
            sgt[(half * 16 + c) * 72 + r] = __float2bfloat16(gp[c] * inv);
    }
    __syncthreads();
#pragma unroll
    for (int v = 0; v < 2; v++) {
        int idx = t + v * 128;  // [0,256): 32 c x 8 chunks of 16B
        int c = idx >> 3, m = idx & 7;
        uint4 d = *(const uint4*)((const char*)sgt + c * 144 + m * 16);
        *(uint4*)((char*)g2t + (((size_t)(b * 32 + c)) * 4096 + (size_t)j0) * 2 + m * 16) = d;
    }
}

// ==================== pass2: y2[i,c] = sum_j exp2(f') * g2t (fused) ====================
// grid (64 iT, 4 b), 128 thr (4 warps x 16 i). Streams phi + g2t chunks (128 j), 2-stage.
__global__ __launch_bounds__(128) void attn_pass2(const __nv_bfloat16* __restrict__ thetab,
                                                  const __nv_bfloat16* __restrict__ phib,
                                                  const __nv_bfloat16* __restrict__ g2t,
                                                  float* __restrict__ y2) {
    __shared__ __align__(16) unsigned char sm[43008];
    // STH[0..5120) SPHI0[5120..15360) SPHI1[15360..25600) SG0[25600..34304) SG1[34304..43008)
    uint32_t smb = smem_u32(sm);
    const int STH = 0, SPHI0 = 5120, SPHI1 = 15360, SG0 = 25600, SG1 = 34304;
    int t = threadIdx.x, wid = t >> 5, lane = t & 31;
    int b = blockIdx.y;
    int i0 = blockIdx.x * 64;

    // load theta tile (64 rows), stride 80
#pragma unroll
    for (int v = 0; v < 2; v++) {
        int idx = t + v * 128;
        int row = idx >> 2, c16 = idx & 3;
        float4 d = *(const float4*)((const char*)thetab + ((size_t)((b << 12) + i0 + row)) * 64 + c16 * 16);
        *(float4*)(sm + STH + row * 80 + c16 * 16) = d;
    }
    __syncthreads();

    uint32_t af[2][4];
#pragma unroll
    for (int kt = 0; kt < 2; kt++) {
        uint32_t a = smb + STH + (wid * 16 + (lane & 15)) * 80 + kt * 32 + (lane >> 4) * 16;
        LDM_X4(af[kt][0], af[kt][1], af[kt][2], af[kt][3], a);
    }

    auto load_chunk = [&](uint32_t sphi, uint32_t sg, int chunk) {
#pragma unroll
        for (int v = 0; v < 4; v++) {
            int idx = t + v * 128;  // [0,512)
            int row = idx >> 2, c16 = idx & 3;
            const char* src = (const char*)phib + ((size_t)((b << 12) + chunk * 128 + row)) * 64 + c16 * 16;
            CP_ASYNC16(smb + sphi + row * 80 + c16 * 16, src);
        }
#pragma unroll
        for (int v = 0; v < 4; v++) {
            int idx = t + v * 128;  // [0,512): 32 rows x 16 chunks of 16B
            int row = idx >> 4, c16 = idx & 15;
            const char* src = (const char*)g2t + (((size_t)(b * 32 + row)) * 4096 + (size_t)(chunk * 128)) * 2 + c16 * 16;
            CP_ASYNC16(smb + sg + row * 272 + c16 * 16, src);
        }
        CP_COMMIT();
    };
    load_chunk(SPHI0, SG0, 0);
    load_chunk(SPHI1, SG1, 1);

    float y2acc[4][4];
#pragma unroll
    for (int cn = 0; cn < 4; cn++)
#pragma unroll
        for (int r = 0; r < 4; r++) y2acc[cn][r] = 0.0f;

    for (int chunk = 0; chunk < 32; chunk++) {
        uint32_t sphi = (chunk & 1) ? SPHI1 : SPHI0;
        uint32_t sg = (chunk & 1) ? SG1 : SG0;
        CP_WAIT1();
        __syncthreads();
#pragma unroll
        for (int p = 0; p < 8; p++) {
            float c[2][4];
#pragma unroll
            for (int half = 0; half < 2; half++) {
                int nt = 2 * p + half;
                uint32_t b0, b1, b2, b3;
                LDM_X4(b0, b1, b2, b3, smb + sphi + (nt * 8 + (lane & 7)) * 80 + (lane >> 3) * 16);
                c[half][0] = 0.0f; c[half][1] = 0.0f; c[half][2] = 0.0f; c[half][3] = 0.0f;
                MMA16816(c[half][0], c[half][1], c[half][2], c[half][3],
                         af[0][0], af[0][1], af[0][2], af[0][3], b0, b1);
                MMA16816(c[half][0], c[half][1], c[half][2], c[half][3],
                         af[1][0], af[1][1], af[1][2], af[1][3], b2, b3);
            }
            uint32_t pa[4];
            pa[0] = pack_bf16x2(ex2f(c[0][0]), ex2f(c[0][1]));
            pa[1] = pack_bf16x2(ex2f(c[0][2]), ex2f(c[0][3]));
            pa[2] = pack_bf16x2(ex2f(c[1][0]), ex2f(c[1][1]));
            pa[3] = pack_bf16x2(ex2f(c[1][2]), ex2f(c[1][3]));
#pragma unroll
            for (int pr = 0; pr < 2; pr++) {  // cn pairs (0,1),(2,3)
                uint32_t u0, u1, u2, u3;
                LDM_X4(u0, u1, u2, u3,
                       smb + sg + ((pr * 2 + (lane >> 4)) * 8 + (lane & 7)) * 272 + p * 32 + ((lane >> 3) & 1) * 16);
                MMA16816(y2acc[pr * 2][0], y2acc[pr * 2][1], y2acc[pr * 2][2], y2acc[pr * 2][3],
                         pa[0], pa[1], pa[2], pa[3], u0, u1);
                MMA16816(y2acc[pr * 2 + 1][0], y2acc[pr * 2 + 1][1], y2acc[pr * 2 + 1][2], y2acc[pr * 2 + 1][3],
                         pa[0], pa[1], pa[2], pa[3], u2, u3);
            }
        }
        __syncthreads();
        if (chunk + 2 < 32) load_chunk(sphi, sg, chunk + 2);
        else CP_COMMIT();
    }

    int q = lane & 3, gq = lane >> 2;
#pragma unroll
    for (int cn = 0; cn < 4; cn++) {
        int col = cn * 8 + q * 2;
        size_t r0 = ((size_t)((b << 12) + i0 + wid * 16 + gq)) * 32;
        size_t r1 = ((size_t)((b << 12) + i0 + wid * 16 + gq + 8)) * 32;
        *(float2*)&y2[r0 + col] = make_float2(y2acc[cn][0], y2acc[cn][1]);
        *(float2*)&y2[r1 + col] = make_float2(y2acc[cn][2], y2acc[cn][3]);
    }
}

// ==================== epilogue: out = (W@y2 + wb + am) * x ====================
__global__ void epilogue(const float* __restrict__ y2, const float* __restrict__ ww,
                         const float* __restrict__ wb, const float* __restrict__ am,
                         const float* __restrict__ x, float* __restrict__ out) {
    __shared__ float sy[64 * 33];
    __shared__ float sw[64 * 32];
    __shared__ float sb[64];
    int t = threadIdx.x;
    for (int l = t; l < 2048; l += 256) sw[l] = ww[l];
    if (t < 64) sb[t] = wb[t];
    int pxBase = blockIdx.x * 64;
    for (int l = t; l < 2048; l += 256) {
        int p = l >> 5, c = l & 31;
        sy[p * 33 + c] = y2[(size_t)(pxBase + p) * 32 + c];
    }
    __syncthreads();
    int px = t & 63, cog = t >> 6;
    int b = pxBase >> 12;
    int pix = (pxBase & 4095) + px;
#pragma unroll
    for (int c16 = 0; c16 < 16; c16++) {
        int co = cog * 16 + c16;
        float a = sb[co];
#pragma unroll
        for (int c = 0; c < 32; c++) a += sw[co * 32 + c] * sy[px * 33 + c];
        int oidx = (b * 64 + co) * 4096 + pix;
        out[oidx] = (a + am[oidx]) * x[oidx];
    }
}

// ==================== launch ====================
extern "C" void kernel_launch(void* const* d_in, const int* in_sizes, int n_in,
                              void* d_out, int out_size) {
    (void)in_sizes; (void)n_in; (void)out_size;
    const float* x = (const float*)d_in[0];
    const float* d1w = (const float*)d_in[1];
    const float* d1b = (const float*)d_in[2];
    const float* d2w = (const float*)d_in[3];
    const float* d2b = (const float*)d_in[4];
    const float* d3w = (const float*)d_in[5];
    const float* d3b = (const float*)d_in[6];
    const float* gw = (const float*)d_in[7];
    const float* gb = (const float*)d_in[8];
    const float* thw = (const float*)d_in[9];
    const float* thb = (const float*)d_in[10];
    const float* phw = (const float*)d_in[11];
    const float* phb = (const float*)d_in[12];
    const float* www = (const float*)d_in[13];
    const float* wwb = (const float*)d_in[14];
    float* out = (float*)d_out;

    float *p_y1, *p_y2c, *p_y3, *p_am, *p_g, *p_y2a;
    __nv_bfloat16 *p_th, *p_ph, *p_g2t;
    cudaGetSymbolAddress((void**)&p_y1, g_y1);
    cudaGetSymbolAddress((void**)&p_y2c, g_y2c);
    cudaGetSymbolAddress((void**)&p_y3, g_y3);
    cudaGetSymbolAddress((void**)&p_am, g_am);
    cudaGetSymbolAddress((void**)&p_th, g_thb);
    cudaGetSymbolAddress((void**)&p_ph, g_phb);
    cudaGetSymbolAddress((void**)&p_g, g_g);
    cudaGetSymbolAddress((void**)&p_g2t, g_g2t);
    cudaGetSymbolAddress((void**)&p_y2a, g_y2a);

    const int AMPROJ_SMEM = (6144 + 8320 + 96) * 4;  // 58240 B
    static bool attr_done = false;
    if (!attr_done) {
        cudaFuncSetAttribute(amproj, cudaFuncAttributeMaxDynamicSharedMemorySize, AMPROJ_SMEM);
        attr_done = true;
    }

    conv3x3_s2<32, 8><<<128, 256>>>(x, p_y1, d1w, d1b, 64, 32, 1);
    conv3x3_s2<16, 4><<<64, 256>>>(p_y1, p_y2c, d2w, d2b, 32, 16, 1);
    conv3x3_s2<8, 2><<<32, 256>>>(p_y2c, p_y3, d3w, d3b, 16, 8, 0);
    amproj<<<128, 384, AMPROJ_SMEM>>>(p_y3, x, thw, thb, phw, phb, gw, gb,
                                      p_am, p_th, p_ph, p_g);
    attn_pass1<<<dim3(64, 4), 128>>>(p_th, p_ph, p_g, p_g2t);
    attn_pass2<<<dim3(64, 4), 128>>>(p_th, p_ph, p_g2t, p_y2a);
    epilogue<<<256, 256>>>(p_y2a, www, wwb, p_am, x, out);
}